// round 13
// baseline (speedup 1.0000x reference)
#include <cuda_runtime.h>
#include <math.h>
#include <stdint.h>

#define B_  2
#define L_  2048
#define E_  1024
#define H_  16
#define DH_ 64
#define M_  (B_*L_)

// GEMM tiling (3-stage cp.async pipeline)
#define BM 128
#define BN 128
#define BK 32
#define SAST 36              // smem k-stride (32 + 4 pad)
#define GEMM_SMEM (3*2*BM*SAST*4)   // 3-stage A+B = 110,592 B

// attention smem: 3-stage sK[3][64][68] + sV[3][64][72] = 107,520 B
#define QK_ST 68
#define V_ST  72
#define ATTN_SMEM (3*(64*QK_ST + 64*V_ST) * 4)

// ---------------- scratch (device globals; no allocation allowed) ----------
__device__ float g_Q[(size_t)B_*H_*L_*DH_];
__device__ float g_K[(size_t)B_*H_*L_*DH_];
__device__ float g_V[(size_t)B_*H_*L_*DH_];
__device__ float g_CTX[(size_t)M_*E_];
__device__ float g_PROJ[(size_t)M_*E_];

__device__ __forceinline__ void mma_tf32(float c[4],
    uint32_t a0, uint32_t a1, uint32_t a2, uint32_t a3,
    uint32_t b0, uint32_t b1)
{
    asm volatile(
        "mma.sync.aligned.m16n8k8.row.col.f32.tf32.tf32.f32 "
        "{%0,%1,%2,%3}, {%4,%5,%6,%7}, {%8,%9}, {%0,%1,%2,%3};"
        : "+f"(c[0]), "+f"(c[1]), "+f"(c[2]), "+f"(c[3])
        : "r"(a0), "r"(a1), "r"(a2), "r"(a3), "r"(b0), "r"(b1));
}

__device__ __forceinline__ void cp16(uint32_t smem_addr, const void* gptr) {
    asm volatile("cp.async.cg.shared.global [%0], [%1], 16;"
                 :: "r"(smem_addr), "l"(gptr));
}
__device__ __forceinline__ void cp_commit() {
    asm volatile("cp.async.commit_group;");
}

// ---------------- tf32 GEMM body, 3-stage cp.async, 1 sync/iter ------------
// out = A[M,K] @ W[N,K]^T + bias ; MODE 0: scatter [B,H,L,DH]; MODE 1: +resid
template<int MODE>
__device__ __forceinline__ void gemm_body(
    const float* __restrict__ A, const float* __restrict__ W,
    const float* __restrict__ bias, const float* __restrict__ resid,
    float* __restrict__ out)
{
    extern __shared__ uint32_t gsm[];
    uint32_t* sA = gsm;                    // [3][BM][SAST]
    uint32_t* sB = gsm + 3*BM*SAST;        // [3][BN][SAST]

    const int t    = threadIdx.x;
    const int m0   = blockIdx.y * BM;
    const int n0   = blockIdx.x * BN;
    const int wid  = t >> 5, lane = t & 31;
    const int wm   = wid >> 2;
    const int wn   = wid & 3;
    const int grp  = lane >> 2;
    const int qd   = lane & 3;

    const int lrow = t >> 3;
    const int lc4  = (t & 7) << 2;

    const float* Ap = A + (size_t)(m0 + lrow) * E_ + lc4;
    const float* Wp = W + (size_t)(n0 + lrow) * E_ + lc4;

    auto issue = [&](int kt, int buf) {
        const int k0 = kt * BK;
        #pragma unroll
        for (int i = 0; i < 4; i++) {
            const int r = buf * BM + lrow + (i << 5);
            cp16((uint32_t)__cvta_generic_to_shared(&sA[r * SAST + lc4]),
                 Ap + k0 + (size_t)(i << 5) * E_);
            cp16((uint32_t)__cvta_generic_to_shared(&sB[r * SAST + lc4]),
                 Wp + k0 + (size_t)(i << 5) * E_);
        }
        cp_commit();
    };

    float c[4][4][4];
    #pragma unroll
    for (int mt = 0; mt < 4; mt++)
        #pragma unroll
        for (int nt = 0; nt < 4; nt++)
            #pragma unroll
            for (int r = 0; r < 4; r++) c[mt][nt][r] = 0.f;

    issue(0, 0);
    issue(1, 1);

    const int NK = E_ / BK;    // 32
    int buf = 0;
    for (int kt = 0; kt < NK; kt++) {
        // tile kt complete (own groups), then make all threads' copies visible
        if (kt < NK - 1) asm volatile("cp.async.wait_group 1;");
        else             asm volatile("cp.async.wait_group 0;");
        __syncthreads();   // also: everyone finished reading buf (kt-1)%3

        if (kt + 2 < NK) {
            int nb = buf + 2; if (nb >= 3) nb -= 3;
            issue(kt + 2, nb);     // writes buf (kt-1)%3 — safe post-barrier
        }

        const uint32_t* cA = sA + buf * BM * SAST;
        const uint32_t* cB = sB + buf * BM * SAST;

        #pragma unroll
        for (int ks = 0; ks < 4; ks++) {
            const int kc = (ks << 3) + qd;
            uint32_t a[4][4], b[4][2];
            #pragma unroll
            for (int mt = 0; mt < 4; mt++) {
                const int r = (wm << 6) + (mt << 4) + grp;
                a[mt][0] = cA[ r      * SAST + kc    ];
                a[mt][1] = cA[(r + 8) * SAST + kc    ];
                a[mt][2] = cA[ r      * SAST + kc + 4];
                a[mt][3] = cA[(r + 8) * SAST + kc + 4];
            }
            #pragma unroll
            for (int nt = 0; nt < 4; nt++) {
                const int r = (wn << 5) + (nt << 3) + grp;
                b[nt][0] = cB[r * SAST + kc    ];
                b[nt][1] = cB[r * SAST + kc + 4];
            }
            #pragma unroll
            for (int mt = 0; mt < 4; mt++)
                #pragma unroll
                for (int nt = 0; nt < 4; nt++)
                    mma_tf32(c[mt][nt], a[mt][0], a[mt][1], a[mt][2], a[mt][3],
                             b[nt][0], b[nt][1]);
        }
        if (++buf == 3) buf = 0;
    }

    #pragma unroll
    for (int mt = 0; mt < 4; mt++) {
        #pragma unroll
        for (int half = 0; half < 2; half++) {
            const int m = m0 + (wm << 6) + (mt << 4) + grp + (half << 3);
            #pragma unroll
            for (int nt = 0; nt < 4; nt++) {
                const int n = n0 + (wn << 5) + (nt << 3) + (qd << 1);
                const float2 bv = *(const float2*)(bias + n);
                float v0 = c[mt][nt][half * 2 + 0] + bv.x;
                float v1 = c[mt][nt][half * 2 + 1] + bv.y;
                if (MODE == 1) {
                    const size_t idx = (size_t)m * E_ + n;
                    const float2 rv = *(const float2*)(resid + idx);
                    float2 o; o.x = v0 + rv.x; o.y = v1 + rv.y;
                    *(float2*)(out + idx) = o;
                } else {
                    const int b = m >> 11;
                    const int l = m & (L_ - 1);
                    const int h = n >> 6;
                    const int d = n & 63;
                    float2 o; o.x = v0; o.y = v1;
                    *(float2*)(out + (((((size_t)b * H_ + h) << 11) + l) << 6) + d) = o;
                }
            }
        }
    }
}

// fused QKV projection: blockIdx.z selects {q,k,v}
__global__ __launch_bounds__(256, 2) void gemm_qkv(
    const float* __restrict__ xq, const float* __restrict__ Wq, const float* __restrict__ bq,
    const float* __restrict__ xk, const float* __restrict__ Wk, const float* __restrict__ bk,
    const float* __restrict__ xv, const float* __restrict__ Wv, const float* __restrict__ bv,
    float* __restrict__ dQ, float* __restrict__ dK, float* __restrict__ dV)
{
    const int z = blockIdx.z;
    const float* A    = (z == 0) ? xq : (z == 1) ? xk : xv;
    const float* W    = (z == 0) ? Wq : (z == 1) ? Wk : Wv;
    const float* bias = (z == 0) ? bq : (z == 1) ? bk : bv;
    float* out        = (z == 0) ? dQ : (z == 1) ? dK : dV;
    gemm_body<0>(A, W, bias, nullptr, out);
}

__global__ __launch_bounds__(256, 2) void gemm_o(
    const float* __restrict__ A, const float* __restrict__ W,
    const float* __restrict__ bias, const float* __restrict__ resid,
    float* __restrict__ out)
{
    gemm_body<1>(A, W, bias, resid, out);
}

// ---------------- tensor-core flash attention (R11 + 3-stage pipeline) -----
// grid (L/128, H, B), block 128 (4 warps). Warp owns 32 q-rows (2 m-tiles).
__global__ __launch_bounds__(128, 2) void attn_tc(
    const float* __restrict__ Qg, const float* __restrict__ Kg,
    const float* __restrict__ Vg, const unsigned char* __restrict__ mask,
    float* __restrict__ CTX)
{
    extern __shared__ uint32_t smu[];
    uint32_t* sKb = smu;                    // [3][64*QK_ST]
    uint32_t* sVb = smu + 3 * 64 * QK_ST;   // [3][64*V_ST]

    const int t    = threadIdx.x;
    const int lane = t & 31, wid = t >> 5;
    const int grp  = lane >> 2, qd = lane & 3;
    const int qbase = wid << 5;             // 32 rows per warp
    const int qt = blockIdx.x, h = blockIdx.y, b = blockIdx.z;

    const float* Qb = Qg + (((size_t)b * H_ + h) * L_ + (qt << 7)) * DH_;
    const float* Kb = Kg + ((size_t)b * H_ + h) * L_ * DH_;
    const float* Vb = Vg + ((size_t)b * H_ + h) * L_ * DH_;

    // Q fragments -> registers (raw fp32 bits; tf32 truncation in HW)
    uint32_t qA[2][8][4];
    #pragma unroll
    for (int mt = 0; mt < 2; mt++) {
        const float* q0 = Qb + (size_t)(qbase + (mt << 4) + grp) * DH_;
        #pragma unroll
        for (int ks = 0; ks < 8; ks++) {
            const int kc = (ks << 3) + qd;
            qA[mt][ks][0] = __float_as_uint(q0[kc]);
            qA[mt][ks][1] = __float_as_uint(q0[(DH_ << 3) + kc]);
            qA[mt][ks][2] = __float_as_uint(q0[kc + 4]);
            qA[mt][ks][3] = __float_as_uint(q0[(DH_ << 3) + kc + 4]);
        }
    }

    float accO[2][8][4];
    #pragma unroll
    for (int mt = 0; mt < 2; mt++)
        #pragma unroll
        for (int nt = 0; nt < 8; nt++)
            #pragma unroll
            for (int r = 0; r < 4; r++) accO[mt][nt][r] = 0.f;
    float mrun[2][2], lrun[2][2];
    #pragma unroll
    for (int mt = 0; mt < 2; mt++) {
        mrun[mt][0] = -1e30f; mrun[mt][1] = -1e30f;
        lrun[mt][0] = 0.f;    lrun[mt][1] = 0.f;
    }

    const int qrow = (qt << 7) + qbase + grp;   // mt0 lo row (global)
    const unsigned char* mbase = mask + ((size_t)b * L_ + qrow) * L_;

    auto issueKV = [&](int kt, int buf) {
        const float* Kt = Kb + ((size_t)kt << 6) * DH_;
        const float* Vt = Vb + ((size_t)kt << 6) * DH_;
        uint32_t* dK = sKb + buf * 64 * QK_ST;
        uint32_t* dV = sVb + buf * 64 * V_ST;
        #pragma unroll
        for (int i = 0; i < 8; i++) {
            const int idx = t + (i << 7);
            const int row = idx >> 4, c4 = (idx & 15) << 2;
            cp16((uint32_t)__cvta_generic_to_shared(&dK[row * QK_ST + c4]),
                 Kt + (row << 6) + c4);
            cp16((uint32_t)__cvta_generic_to_shared(&dV[row * V_ST + c4]),
                 Vt + (row << 6) + c4);
        }
        cp_commit();
    };

    issueKV(0, 0);
    issueKV(1, 1);

    const int NT = L_ / 64;   // 32
    int buf = 0;
    for (int kt = 0; kt < NT; kt++) {
        // prefetch mask bytes for this tile (independent of cp.async)
        uchar2 mk[2][2][8];
        const int colb = (kt << 6) + (qd << 1);
        #pragma unroll
        for (int mt = 0; mt < 2; mt++)
            #pragma unroll
            for (int hf = 0; hf < 2; hf++) {
                const unsigned char* mp =
                    mbase + (size_t)((mt << 4) + (hf << 3)) * L_ + colb;
                #pragma unroll
                for (int nt = 0; nt < 8; nt++)
                    mk[mt][hf][nt] = *(const uchar2*)(mp + (nt << 3));
            }

        if (kt < NT - 1) asm volatile("cp.async.wait_group 1;");
        else             asm volatile("cp.async.wait_group 0;");
        __syncthreads();   // copies visible + all done reading buf (kt-1)%3

        if (kt + 2 < NT) {
            int nb = buf + 2; if (nb >= 3) nb -= 3;
            issueKV(kt + 2, nb);   // writes buf (kt-1)%3 — safe post-barrier
        }

        const uint32_t* K = sKb + buf * 64 * QK_ST;
        const uint32_t* V = sVb + buf * 64 * V_ST;

        // ---- S = Q K^T (32 x 64 per warp, B-frags shared across m-tiles) --
        float s[2][8][4];
        #pragma unroll
        for (int mt = 0; mt < 2; mt++)
            #pragma unroll
            for (int nt = 0; nt < 8; nt++)
                #pragma unroll
                for (int r = 0; r < 4; r++) s[mt][nt][r] = 0.f;

        #pragma unroll
        for (int ks = 0; ks < 8; ks++) {
            const int kc = (ks << 3) + qd;
            #pragma unroll
            for (int nt = 0; nt < 8; nt++) {
                const uint32_t b0 = K[((nt << 3) + grp) * QK_ST + kc    ];
                const uint32_t b1 = K[((nt << 3) + grp) * QK_ST + kc + 4];
                mma_tf32(s[0][nt], qA[0][ks][0], qA[0][ks][1], qA[0][ks][2], qA[0][ks][3], b0, b1);
                mma_tf32(s[1][nt], qA[1][ks][0], qA[1][ks][1], qA[1][ks][2], qA[1][ks][3], b0, b1);
            }
        }

        // ---- scale + mask + online softmax per m-tile ----
        #pragma unroll
        for (int mt = 0; mt < 2; mt++) {
            #pragma unroll
            for (int nt = 0; nt < 8; nt++) {
                s[mt][nt][0] = mk[mt][0][nt].x ? -1e30f : s[mt][nt][0] * 0.125f;
                s[mt][nt][1] = mk[mt][0][nt].y ? -1e30f : s[mt][nt][1] * 0.125f;
                s[mt][nt][2] = mk[mt][1][nt].x ? -1e30f : s[mt][nt][2] * 0.125f;
                s[mt][nt][3] = mk[mt][1][nt].y ? -1e30f : s[mt][nt][3] * 0.125f;
            }
            float mlo = -1e30f, mhi = -1e30f;
            #pragma unroll
            for (int nt = 0; nt < 8; nt++) {
                mlo = fmaxf(mlo, fmaxf(s[mt][nt][0], s[mt][nt][1]));
                mhi = fmaxf(mhi, fmaxf(s[mt][nt][2], s[mt][nt][3]));
            }
            mlo = fmaxf(mlo, __shfl_xor_sync(0xffffffffu, mlo, 1));
            mlo = fmaxf(mlo, __shfl_xor_sync(0xffffffffu, mlo, 2));
            mhi = fmaxf(mhi, __shfl_xor_sync(0xffffffffu, mhi, 1));
            mhi = fmaxf(mhi, __shfl_xor_sync(0xffffffffu, mhi, 2));

            const float mn0 = fmaxf(mrun[mt][0], mlo);
            const float mn1 = fmaxf(mrun[mt][1], mhi);
            const float al0 = __expf(mrun[mt][0] - mn0);
            const float al1 = __expf(mrun[mt][1] - mn1);
            mrun[mt][0] = mn0; mrun[mt][1] = mn1;

            float rs0 = 0.f, rs1 = 0.f;
            #pragma unroll
            for (int nt = 0; nt < 8; nt++) {
                s[mt][nt][0] = __expf(s[mt][nt][0] - mn0);
                s[mt][nt][1] = __expf(s[mt][nt][1] - mn0);
                s[mt][nt][2] = __expf(s[mt][nt][2] - mn1);
                s[mt][nt][3] = __expf(s[mt][nt][3] - mn1);
                rs0 += s[mt][nt][0] + s[mt][nt][1];
                rs1 += s[mt][nt][2] + s[mt][nt][3];
            }
            rs0 += __shfl_xor_sync(0xffffffffu, rs0, 1);
            rs0 += __shfl_xor_sync(0xffffffffu, rs0, 2);
            rs1 += __shfl_xor_sync(0xffffffffu, rs1, 1);
            rs1 += __shfl_xor_sync(0xffffffffu, rs1, 2);
            lrun[mt][0] = lrun[mt][0] * al0 + rs0;
            lrun[mt][1] = lrun[mt][1] * al1 + rs1;

            #pragma unroll
            for (int nt = 0; nt < 8; nt++) {
                accO[mt][nt][0] *= al0; accO[mt][nt][1] *= al0;
                accO[mt][nt][2] *= al1; accO[mt][nt][3] *= al1;
            }
        }

        // ---- O += P V (A-frags via quad shuffles; B shared across mt) ----
        const int basel = lane & 28;
        const int srcA = basel | (qd >> 1);
        const int srcB = srcA + 2;
        const bool odd = (qd & 1);
        #pragma unroll
        for (int j = 0; j < 8; j++) {
            uint32_t a[2][4];
            #pragma unroll
            for (int mt = 0; mt < 2; mt++) {
                const uint32_t p0 = __float_as_uint(s[mt][j][0]);
                const uint32_t p1 = __float_as_uint(s[mt][j][1]);
                const uint32_t p2 = __float_as_uint(s[mt][j][2]);
                const uint32_t p3 = __float_as_uint(s[mt][j][3]);
                const uint32_t x0 = __shfl_sync(0xffffffffu, p0, srcA);
                const uint32_t y0 = __shfl_sync(0xffffffffu, p1, srcA);
                const uint32_t x1 = __shfl_sync(0xffffffffu, p2, srcA);
                const uint32_t y1 = __shfl_sync(0xffffffffu, p3, srcA);
                const uint32_t x2 = __shfl_sync(0xffffffffu, p0, srcB);
                const uint32_t y2 = __shfl_sync(0xffffffffu, p1, srcB);
                const uint32_t x3 = __shfl_sync(0xffffffffu, p2, srcB);
                const uint32_t y3 = __shfl_sync(0xffffffffu, p3, srcB);
                a[mt][0] = odd ? y0 : x0;
                a[mt][1] = odd ? y1 : x1;
                a[mt][2] = odd ? y2 : x2;
                a[mt][3] = odd ? y3 : x3;
            }
            const int kr0 = ((j << 3) + qd) * V_ST;
            const int kr1 = ((j << 3) + qd + 4) * V_ST;
            #pragma unroll
            for (int nt = 0; nt < 8; nt++) {
                const uint32_t b0 = V[kr0 + (nt << 3) + grp];
                const uint32_t b1 = V[kr1 + (nt << 3) + grp];
                mma_tf32(accO[0][nt], a[0][0], a[0][1], a[0][2], a[0][3], b0, b1);
                mma_tf32(accO[1][nt], a[1][0], a[1][1], a[1][2], a[1][3], b0, b1);
            }
        }
        if (++buf == 3) buf = 0;
    }

    // ---- epilogue ----
    #pragma unroll
    for (int mt = 0; mt < 2; mt++) {
        const float inv0 = 1.0f / lrun[mt][0];
        const float inv1 = 1.0f / lrun[mt][1];
        float* Cp = CTX + ((size_t)b * L_ + qrow + (mt << 4)) * E_ + (h << 6);
        #pragma unroll
        for (int nt = 0; nt < 8; nt++) {
            const int col = (nt << 3) + (qd << 1);
            float2 o0; o0.x = accO[mt][nt][0] * inv0; o0.y = accO[mt][nt][1] * inv0;
            *(float2*)(Cp + col) = o0;
            float2 o1; o1.x = accO[mt][nt][2] * inv1; o1.y = accO[mt][nt][3] * inv1;
            *(float2*)(Cp + (size_t)8 * E_ + col) = o1;
        }
    }
}

// ---------------- LayerNorm over E=1024, one row per block -----------------
__global__ __launch_bounds__(256) void ln_kernel(
    const float* __restrict__ X, const float* __restrict__ gamma,
    const float* __restrict__ beta, float* __restrict__ out)
{
    __shared__ float red[8];
    __shared__ float s_mu, s_rstd;
    const int row = blockIdx.x;
    const int t = threadIdx.x;

    float4 v = ((const float4*)(X + (size_t)row * E_))[t];
    float s = v.x + v.y + v.z + v.w;
    #pragma unroll
    for (int off = 16; off >= 1; off >>= 1) s += __shfl_xor_sync(0xffffffffu, s, off);
    if ((t & 31) == 0) red[t >> 5] = s;
    __syncthreads();
    if (t == 0) {
        float tot = 0.f;
        #pragma unroll
        for (int k = 0; k < 8; k++) tot += red[k];
        s_mu = tot * (1.0f / E_);
    }
    __syncthreads();
    const float mu = s_mu;

    float dx = v.x - mu, dy = v.y - mu, dz = v.z - mu, dw = v.w - mu;
    float sq = dx * dx + dy * dy + dz * dz + dw * dw;
    #pragma unroll
    for (int off = 16; off >= 1; off >>= 1) sq += __shfl_xor_sync(0xffffffffu, sq, off);
    __syncthreads();
    if ((t & 31) == 0) red[t >> 5] = sq;
    __syncthreads();
    if (t == 0) {
        float tot = 0.f;
        #pragma unroll
        for (int k = 0; k < 8; k++) tot += red[k];
        s_rstd = rsqrtf(tot * (1.0f / E_) + 1e-6f);
    }
    __syncthreads();
    const float rstd = s_rstd;

    float4 g  = ((const float4*)gamma)[t];
    float4 be = ((const float4*)beta)[t];
    float4 o;
    o.x = dx * rstd * g.x + be.x;
    o.y = dy * rstd * g.y + be.y;
    o.z = dz * rstd * g.z + be.z;
    o.w = dw * rstd * g.w + be.w;
    ((float4*)(out + (size_t)row * E_))[t] = o;
}

// ---------------- launch ---------------------------------------------------
extern "C" void kernel_launch(void* const* d_in, const int* in_sizes, int n_in,
                              void* d_out, int out_size)
{
    const float* xq    = (const float*)d_in[0];
    const float* xk    = (const float*)d_in[1];
    const float* xv    = (const float*)d_in[2];
    const unsigned char* mask = (const unsigned char*)d_in[3];
    const float* Wq = (const float*)d_in[4];
    const float* bq = (const float*)d_in[5];
    const float* Wk = (const float*)d_in[6];
    const float* bk = (const float*)d_in[7];
    const float* Wv = (const float*)d_in[8];
    const float* bv = (const float*)d_in[9];
    const float* Wo = (const float*)d_in[10];
    const float* bo = (const float*)d_in[11];
    const float* gamma = (const float*)d_in[12];
    const float* beta  = (const float*)d_in[13];
    float* out = (float*)d_out;

    float *dQ, *dK, *dV, *dCTX, *dPROJ;
    cudaGetSymbolAddress((void**)&dQ,    g_Q);
    cudaGetSymbolAddress((void**)&dK,    g_K);
    cudaGetSymbolAddress((void**)&dV,    g_V);
    cudaGetSymbolAddress((void**)&dCTX,  g_CTX);
    cudaGetSymbolAddress((void**)&dPROJ, g_PROJ);

    cudaFuncSetAttribute(gemm_qkv,
                         cudaFuncAttributeMaxDynamicSharedMemorySize, GEMM_SMEM);
    cudaFuncSetAttribute(gemm_o,
                         cudaFuncAttributeMaxDynamicSharedMemorySize, GEMM_SMEM);
    cudaFuncSetAttribute(attn_tc,
                         cudaFuncAttributeMaxDynamicSharedMemorySize, ATTN_SMEM);

    gemm_qkv<<<dim3(E_ / BN, M_ / BM, 3), 256, GEMM_SMEM>>>(
        xq, Wq, bq, xk, Wk, bk, xv, Wv, bv, dQ, dK, dV);

    attn_tc<<<dim3(L_ / 128, H_, B_), 128, ATTN_SMEM>>>(dQ, dK, dV, mask, dCTX);

    gemm_o<<<dim3(E_ / BN, M_ / BM), 256, GEMM_SMEM>>>(dCTX, Wo, bo, xq, dPROJ);

    ln_kernel<<<M_, 256>>>(dPROJ, gamma, beta, out);
}

// round 14
// speedup vs baseline: 1.3623x; 1.3623x over previous
#include <cuda_runtime.h>
#include <cuda_fp16.h>
#include <math.h>
#include <stdint.h>

#define B_  2
#define L_  2048
#define E_  1024
#define H_  16
#define DH_ 64
#define M_  (B_*L_)

// GEMM tiling (tf32, 2-stage cp.async)
#define BM 128
#define BN 128
#define BK 32
#define SAST 36
#define GEMM_SMEM (2*2*BM*SAST*4)

// attention smem (fp16): 2 stages x (K + V^T) x 64 rows x 72 halves
#define KH_ST 72
#define ATTN_SMEM (2*2*64*KH_ST*2)   // 36,864 B

// ---------------- scratch (device globals; no allocation allowed) ----------
__device__ __half g_Qh [(size_t)B_*H_*L_*DH_];
__device__ __half g_Kh [(size_t)B_*H_*L_*DH_];
__device__ __half g_VTh[(size_t)B_*H_*DH_*L_];   // [b,h,dh,l]
__device__ float  g_CTX[(size_t)M_*E_];
__device__ float  g_PROJ[(size_t)M_*E_];

__device__ __forceinline__ void mma_tf32(float c[4],
    uint32_t a0, uint32_t a1, uint32_t a2, uint32_t a3,
    uint32_t b0, uint32_t b1)
{
    asm volatile(
        "mma.sync.aligned.m16n8k8.row.col.f32.tf32.tf32.f32 "
        "{%0,%1,%2,%3}, {%4,%5,%6,%7}, {%8,%9}, {%0,%1,%2,%3};"
        : "+f"(c[0]), "+f"(c[1]), "+f"(c[2]), "+f"(c[3])
        : "r"(a0), "r"(a1), "r"(a2), "r"(a3), "r"(b0), "r"(b1));
}

__device__ __forceinline__ void mma_f16(float c[4],
    uint32_t a0, uint32_t a1, uint32_t a2, uint32_t a3,
    uint32_t b0, uint32_t b1)
{
    asm volatile(
        "mma.sync.aligned.m16n8k16.row.col.f32.f16.f16.f32 "
        "{%0,%1,%2,%3}, {%4,%5,%6,%7}, {%8,%9}, {%0,%1,%2,%3};"
        : "+f"(c[0]), "+f"(c[1]), "+f"(c[2]), "+f"(c[3])
        : "r"(a0), "r"(a1), "r"(a2), "r"(a3), "r"(b0), "r"(b1));
}

// pack two fp32 into half2 {lo, hi} (first PTX source = high half)
__device__ __forceinline__ uint32_t f2h2(float lo, float hi) {
    uint32_t r;
    asm("cvt.rn.f16x2.f32 %0, %1, %2;" : "=r"(r) : "f"(hi), "f"(lo));
    return r;
}

__device__ __forceinline__ void cp16(uint32_t smem_addr, const void* gptr) {
    asm volatile("cp.async.cg.shared.global [%0], [%1], 16;"
                 :: "r"(smem_addr), "l"(gptr));
}
__device__ __forceinline__ void cp_commit() {
    asm volatile("cp.async.commit_group;");
}

// ---------------- tf32 GEMM body, 2-stage cp.async --------------------------
// MODE 0: half scatter [B,H,L,DH];  MODE 2: half scatter transposed [B,H,DH,L]
// MODE 1: fp32 [M,N] + resid
template<int MODE>
__device__ __forceinline__ void gemm_body(
    const float* __restrict__ A, const float* __restrict__ W,
    const float* __restrict__ bias, const float* __restrict__ resid,
    void* __restrict__ outv)
{
    extern __shared__ uint32_t gsm[];
    uint32_t* sA = gsm;                    // [2][BM][SAST]
    uint32_t* sB = gsm + 2*BM*SAST;        // [2][BN][SAST]

    const int t    = threadIdx.x;
    const int m0   = blockIdx.y * BM;
    const int n0   = blockIdx.x * BN;
    const int wid  = t >> 5, lane = t & 31;
    const int wm   = wid >> 2;
    const int wn   = wid & 3;
    const int grp  = lane >> 2;
    const int qd   = lane & 3;

    const int lrow = t >> 3;
    const int lc4  = (t & 7) << 2;

    const float* Ap = A + (size_t)(m0 + lrow) * E_ + lc4;
    const float* Wp = W + (size_t)(n0 + lrow) * E_ + lc4;

    auto issue = [&](int k0, int buf) {
        #pragma unroll
        for (int i = 0; i < 4; i++) {
            const int r = buf * BM + lrow + (i << 5);
            cp16((uint32_t)__cvta_generic_to_shared(&sA[r * SAST + lc4]),
                 Ap + k0 + (size_t)(i << 5) * E_);
            cp16((uint32_t)__cvta_generic_to_shared(&sB[r * SAST + lc4]),
                 Wp + k0 + (size_t)(i << 5) * E_);
        }
        cp_commit();
    };

    float c[4][4][4];
    #pragma unroll
    for (int mt = 0; mt < 4; mt++)
        #pragma unroll
        for (int nt = 0; nt < 4; nt++)
            #pragma unroll
            for (int r = 0; r < 4; r++) c[mt][nt][r] = 0.f;

    issue(0, 0);
    const int NK = E_ / BK;    // 32
    for (int kt = 0; kt < NK; kt++) {
        const int cur = kt & 1;
        if (kt + 1 < NK) {
            issue((kt + 1) * BK, cur ^ 1);
            asm volatile("cp.async.wait_group 1;");
        } else {
            asm volatile("cp.async.wait_group 0;");
        }
        __syncthreads();

        const uint32_t* cA = sA + cur * BM * SAST;
        const uint32_t* cB = sB + cur * BM * SAST;

        #pragma unroll
        for (int ks = 0; ks < 4; ks++) {
            const int kc = (ks << 3) + qd;
            uint32_t a[4][4], b[4][2];
            #pragma unroll
            for (int mt = 0; mt < 4; mt++) {
                const int r = (wm << 6) + (mt << 4) + grp;
                a[mt][0] = cA[ r      * SAST + kc    ];
                a[mt][1] = cA[(r + 8) * SAST + kc    ];
                a[mt][2] = cA[ r      * SAST + kc + 4];
                a[mt][3] = cA[(r + 8) * SAST + kc + 4];
            }
            #pragma unroll
            for (int nt = 0; nt < 4; nt++) {
                const int r = (wn << 5) + (nt << 3) + grp;
                b[nt][0] = cB[r * SAST + kc    ];
                b[nt][1] = cB[r * SAST + kc + 4];
            }
            #pragma unroll
            for (int mt = 0; mt < 4; mt++)
                #pragma unroll
                for (int nt = 0; nt < 4; nt++)
                    mma_tf32(c[mt][nt], a[mt][0], a[mt][1], a[mt][2], a[mt][3],
                             b[nt][0], b[nt][1]);
        }
        __syncthreads();
    }

    #pragma unroll
    for (int mt = 0; mt < 4; mt++) {
        #pragma unroll
        for (int half = 0; half < 2; half++) {
            const int m = m0 + (wm << 6) + (mt << 4) + grp + (half << 3);
            #pragma unroll
            for (int nt = 0; nt < 4; nt++) {
                const int n = n0 + (wn << 5) + (nt << 3) + (qd << 1);
                const float2 bv = *(const float2*)(bias + n);
                float v0 = c[mt][nt][half * 2 + 0] + bv.x;
                float v1 = c[mt][nt][half * 2 + 1] + bv.y;
                if (MODE == 1) {
                    float* o = (float*)outv;
                    const size_t idx = (size_t)m * E_ + n;
                    const float2 rv = *(const float2*)(resid + idx);
                    float2 ov; ov.x = v0 + rv.x; ov.y = v1 + rv.y;
                    *(float2*)(o + idx) = ov;
                } else if (MODE == 0) {
                    __half* o = (__half*)outv;
                    const int b = m >> 11;
                    const int l = m & (L_ - 1);
                    const int h = n >> 6;
                    const int d = n & 63;
                    *(__half2*)(o + (((((size_t)b * H_ + h) << 11) + l) << 6) + d) =
                        __floats2half2_rn(v0, v1);
                } else {
                    __half* o = (__half*)outv;    // V^T: [b,h,dh,l]
                    const int b = m >> 11;
                    const int l = m & (L_ - 1);
                    const int h = n >> 6;
                    const int d = n & 63;
                    const size_t base = (((size_t)b * H_ + h) * DH_ + d) * L_ + l;
                    o[base]      = __float2half_rn(v0);
                    o[base + L_] = __float2half_rn(v1);   // d+1
                }
            }
        }
    }
}

// fused QKV projection: blockIdx.z selects {q,k,v}
__global__ __launch_bounds__(256, 2) void gemm_qkv(
    const float* __restrict__ xq, const float* __restrict__ Wq, const float* __restrict__ bq,
    const float* __restrict__ xk, const float* __restrict__ Wk, const float* __restrict__ bk,
    const float* __restrict__ xv, const float* __restrict__ Wv, const float* __restrict__ bv,
    __half* __restrict__ dQ, __half* __restrict__ dK, __half* __restrict__ dVT)
{
    const int z = blockIdx.z;
    if (z == 0)      gemm_body<0>(xq, Wq, bq, nullptr, dQ);
    else if (z == 1) gemm_body<0>(xk, Wk, bk, nullptr, dK);
    else             gemm_body<2>(xv, Wv, bv, nullptr, dVT);
}

__global__ __launch_bounds__(256, 2) void gemm_o(
    const float* __restrict__ A, const float* __restrict__ W,
    const float* __restrict__ bias, const float* __restrict__ resid,
    float* __restrict__ out)
{
    gemm_body<1>(A, W, bias, resid, out);
}

// ---------------- fp16 tensor-core flash attention --------------------------
// grid (L/128, H, B), block 128 (4 warps). Warp owns 32 q-rows (2 m-tiles).
// m16n8k16; P-fragment register-resident (no shuffles); V stored transposed.
__global__ __launch_bounds__(128, 2) void attn_tc(
    const __half* __restrict__ Qg, const __half* __restrict__ Kg,
    const __half* __restrict__ VTg, const unsigned char* __restrict__ mask,
    float* __restrict__ CTX)
{
    extern __shared__ __half smh[];
    __half* sKb = smh;                   // [2][64*KH_ST]
    __half* sVb = smh + 2 * 64 * KH_ST;  // [2][64*KH_ST]  (V^T: rows=dh, cols=key)

    const int t    = threadIdx.x;
    const int lane = t & 31, wid = t >> 5;
    const int grp  = lane >> 2, qd = lane & 3;
    const int qbase = wid << 5;             // 32 rows per warp
    const int qt = blockIdx.x, h = blockIdx.y, b = blockIdx.z;

    const __half* Qb  = Qg  + (((size_t)b * H_ + h) * L_ + (qt << 7)) * DH_;
    const __half* Kb  = Kg  + ((size_t)b * H_ + h) * L_ * DH_;
    const __half* VTb = VTg + ((size_t)b * H_ + h) * DH_ * L_;

    // Q fragments -> registers (half2-packed)
    uint32_t qA[2][4][4];
    #pragma unroll
    for (int mt = 0; mt < 2; mt++) {
        const __half* q0 = Qb + (size_t)(qbase + (mt << 4) + grp) * DH_;
        #pragma unroll
        for (int ks = 0; ks < 4; ks++) {
            const int kc = (ks << 4) + (qd << 1);
            qA[mt][ks][0] = *(const uint32_t*)(q0 + kc);
            qA[mt][ks][1] = *(const uint32_t*)(q0 + (DH_ << 3) + kc);
            qA[mt][ks][2] = *(const uint32_t*)(q0 + kc + 8);
            qA[mt][ks][3] = *(const uint32_t*)(q0 + (DH_ << 3) + kc + 8);
        }
    }

    float accO[2][8][4];
    #pragma unroll
    for (int mt = 0; mt < 2; mt++)
        #pragma unroll
        for (int nt = 0; nt < 8; nt++)
            #pragma unroll
            for (int r = 0; r < 4; r++) accO[mt][nt][r] = 0.f;
    float mrun[2][2], lrun[2][2];
    #pragma unroll
    for (int mt = 0; mt < 2; mt++) {
        mrun[mt][0] = -1e30f; mrun[mt][1] = -1e30f;
        lrun[mt][0] = 0.f;    lrun[mt][1] = 0.f;
    }

    const int qrow = (qt << 7) + qbase + grp;
    const unsigned char* mbase = mask + ((size_t)b * L_ + qrow) * L_;

    auto issueKV = [&](int kt, int buf) {
        const __half* Kt = Kb + ((size_t)kt << 6) * DH_;   // 64 key rows x 64 dh
        const __half* Vt = VTb + (kt << 6);                // 64 dh rows, key col offset
        __half* dK = sKb + buf * 64 * KH_ST;
        __half* dV = sVb + buf * 64 * KH_ST;
        #pragma unroll
        for (int i = 0; i < 4; i++) {
            const int idx = t + (i << 7);
            const int row = idx >> 3, ch = (idx & 7) << 3;   // 8 halves = 16B
            cp16((uint32_t)__cvta_generic_to_shared(dK + row * KH_ST + ch),
                 Kt + (row << 6) + ch);
            cp16((uint32_t)__cvta_generic_to_shared(dV + row * KH_ST + ch),
                 Vt + (size_t)row * L_ + ch);
        }
        cp_commit();
    };

    issueKV(0, 0);

    const int NT = L_ / 64;   // 32
    for (int kt = 0; kt < NT; kt++) {
        const int cur = kt & 1;
        if (kt + 1 < NT) issueKV(kt + 1, cur ^ 1);

        // prefetch mask bytes for this tile
        uchar2 mk[2][2][8];
        const int colb = (kt << 6) + (qd << 1);
        #pragma unroll
        for (int mt = 0; mt < 2; mt++)
            #pragma unroll
            for (int hf = 0; hf < 2; hf++) {
                const unsigned char* mp =
                    mbase + (size_t)((mt << 4) + (hf << 3)) * L_ + colb;
                #pragma unroll
                for (int nt = 0; nt < 8; nt++)
                    mk[mt][hf][nt] = *(const uchar2*)(mp + (nt << 3));
            }

        if (kt + 1 < NT) asm volatile("cp.async.wait_group 1;");
        else             asm volatile("cp.async.wait_group 0;");
        __syncthreads();

        const __half* K = sKb + cur * 64 * KH_ST;
        const __half* V = sVb + cur * 64 * KH_ST;

        // ---- S = Q K^T (32 x 64 per warp; k16 MMAs; B-frags shared) ----
        float s[2][8][4];
        #pragma unroll
        for (int mt = 0; mt < 2; mt++)
            #pragma unroll
            for (int nt = 0; nt < 8; nt++)
                #pragma unroll
                for (int r = 0; r < 4; r++) s[mt][nt][r] = 0.f;

        #pragma unroll
        for (int ks = 0; ks < 4; ks++) {
            const int kc = (ks << 4) + (qd << 1);
            #pragma unroll
            for (int nt = 0; nt < 8; nt++) {
                const __half* kr = K + ((nt << 3) + grp) * KH_ST + kc;
                const uint32_t b0 = *(const uint32_t*)(kr);
                const uint32_t b1 = *(const uint32_t*)(kr + 8);
                mma_f16(s[0][nt], qA[0][ks][0], qA[0][ks][1], qA[0][ks][2], qA[0][ks][3], b0, b1);
                mma_f16(s[1][nt], qA[1][ks][0], qA[1][ks][1], qA[1][ks][2], qA[1][ks][3], b0, b1);
            }
        }

        // ---- scale + mask + online softmax per m-tile ----
        #pragma unroll
        for (int mt = 0; mt < 2; mt++) {
            #pragma unroll
            for (int nt = 0; nt < 8; nt++) {
                s[mt][nt][0] = mk[mt][0][nt].x ? -1e30f : s[mt][nt][0] * 0.125f;
                s[mt][nt][1] = mk[mt][0][nt].y ? -1e30f : s[mt][nt][1] * 0.125f;
                s[mt][nt][2] = mk[mt][1][nt].x ? -1e30f : s[mt][nt][2] * 0.125f;
                s[mt][nt][3] = mk[mt][1][nt].y ? -1e30f : s[mt][nt][3] * 0.125f;
            }
            float mlo = -1e30f, mhi = -1e30f;
            #pragma unroll
            for (int nt = 0; nt < 8; nt++) {
                mlo = fmaxf(mlo, fmaxf(s[mt][nt][0], s[mt][nt][1]));
                mhi = fmaxf(mhi, fmaxf(s[mt][nt][2], s[mt][nt][3]));
            }
            mlo = fmaxf(mlo, __shfl_xor_sync(0xffffffffu, mlo, 1));
            mlo = fmaxf(mlo, __shfl_xor_sync(0xffffffffu, mlo, 2));
            mhi = fmaxf(mhi, __shfl_xor_sync(0xffffffffu, mhi, 1));
            mhi = fmaxf(mhi, __shfl_xor_sync(0xffffffffu, mhi, 2));

            const float mn0 = fmaxf(mrun[mt][0], mlo);
            const float mn1 = fmaxf(mrun[mt][1], mhi);
            const float al0 = __expf(mrun[mt][0] - mn0);
            const float al1 = __expf(mrun[mt][1] - mn1);
            mrun[mt][0] = mn0; mrun[mt][1] = mn1;

            float rs0 = 0.f, rs1 = 0.f;
            #pragma unroll
            for (int nt = 0; nt < 8; nt++) {
                s[mt][nt][0] = __expf(s[mt][nt][0] - mn0);
                s[mt][nt][1] = __expf(s[mt][nt][1] - mn0);
                s[mt][nt][2] = __expf(s[mt][nt][2] - mn1);
                s[mt][nt][3] = __expf(s[mt][nt][3] - mn1);
                rs0 += s[mt][nt][0] + s[mt][nt][1];
                rs1 += s[mt][nt][2] + s[mt][nt][3];
            }
            rs0 += __shfl_xor_sync(0xffffffffu, rs0, 1);
            rs0 += __shfl_xor_sync(0xffffffffu, rs0, 2);
            rs1 += __shfl_xor_sync(0xffffffffu, rs1, 1);
            rs1 += __shfl_xor_sync(0xffffffffu, rs1, 2);
            lrun[mt][0] = lrun[mt][0] * al0 + rs0;
            lrun[mt][1] = lrun[mt][1] * al1 + rs1;

            #pragma unroll
            for (int nt = 0; nt < 8; nt++) {
                accO[mt][nt][0] *= al0; accO[mt][nt][1] *= al0;
                accO[mt][nt][2] *= al1; accO[mt][nt][3] *= al1;
            }
        }

        // ---- O += P V : P frag register-resident (C-frag == A-frag layout) --
        #pragma unroll
        for (int kc = 0; kc < 4; kc++) {
            uint32_t pa[2][4];
            #pragma unroll
            for (int mt = 0; mt < 2; mt++) {
                pa[mt][0] = f2h2(s[mt][2*kc  ][0], s[mt][2*kc  ][1]);
                pa[mt][1] = f2h2(s[mt][2*kc  ][2], s[mt][2*kc  ][3]);
                pa[mt][2] = f2h2(s[mt][2*kc+1][0], s[mt][2*kc+1][1]);
                pa[mt][3] = f2h2(s[mt][2*kc+1][2], s[mt][2*kc+1][3]);
            }
            const int kcol = (kc << 4) + (qd << 1);
            #pragma unroll
            for (int nt = 0; nt < 8; nt++) {
                const __half* vr = V + ((nt << 3) + grp) * KH_ST + kcol;
                const uint32_t b0 = *(const uint32_t*)(vr);
                const uint32_t b1 = *(const uint32_t*)(vr + 8);
                mma_f16(accO[0][nt], pa[0][0], pa[0][1], pa[0][2], pa[0][3], b0, b1);
                mma_f16(accO[1][nt], pa[1][0], pa[1][1], pa[1][2], pa[1][3], b0, b1);
            }
        }
        __syncthreads();   // all warps done with buf `cur` before its reuse
    }

    // ---- epilogue ----
    #pragma unroll
    for (int mt = 0; mt < 2; mt++) {
        const float inv0 = 1.0f / lrun[mt][0];
        const float inv1 = 1.0f / lrun[mt][1];
        float* Cp = CTX + ((size_t)b * L_ + qrow + (mt << 4)) * E_ + (h << 6);
        #pragma unroll
        for (int nt = 0; nt < 8; nt++) {
            const int col = (nt << 3) + (qd << 1);
            float2 o0; o0.x = accO[mt][nt][0] * inv0; o0.y = accO[mt][nt][1] * inv0;
            *(float2*)(Cp + col) = o0;
            float2 o1; o1.x = accO[mt][nt][2] * inv1; o1.y = accO[mt][nt][3] * inv1;
            *(float2*)(Cp + (size_t)8 * E_ + col) = o1;
        }
    }
}

// ---------------- LayerNorm over E=1024, one row per block -----------------
__global__ __launch_bounds__(256) void ln_kernel(
    const float* __restrict__ X, const float* __restrict__ gamma,
    const float* __restrict__ beta, float* __restrict__ out)
{
    __shared__ float red[8];
    __shared__ float s_mu, s_rstd;
    const int row = blockIdx.x;
    const int t = threadIdx.x;

    float4 v = ((const float4*)(X + (size_t)row * E_))[t];
    float s = v.x + v.y + v.z + v.w;
    #pragma unroll
    for (int off = 16; off >= 1; off >>= 1) s += __shfl_xor_sync(0xffffffffu, s, off);
    if ((t & 31) == 0) red[t >> 5] = s;
    __syncthreads();
    if (t == 0) {
        float tot = 0.f;
        #pragma unroll
        for (int k = 0; k < 8; k++) tot += red[k];
        s_mu = tot * (1.0f / E_);
    }
    __syncthreads();
    const float mu = s_mu;

    float dx = v.x - mu, dy = v.y - mu, dz = v.z - mu, dw = v.w - mu;
    float sq = dx * dx + dy * dy + dz * dz + dw * dw;
    #pragma unroll
    for (int off = 16; off >= 1; off >>= 1) sq += __shfl_xor_sync(0xffffffffu, sq, off);
    __syncthreads();
    if ((t & 31) == 0) red[t >> 5] = sq;
    __syncthreads();
    if (t == 0) {
        float tot = 0.f;
        #pragma unroll
        for (int k = 0; k < 8; k++) tot += red[k];
        s_rstd = rsqrtf(tot * (1.0f / E_) + 1e-6f);
    }
    __syncthreads();
    const float rstd = s_rstd;

    float4 g  = ((const float4*)gamma)[t];
    float4 be = ((const float4*)beta)[t];
    float4 o;
    o.x = dx * rstd * g.x + be.x;
    o.y = dy * rstd * g.y + be.y;
    o.z = dz * rstd * g.z + be.z;
    o.w = dw * rstd * g.w + be.w;
    ((float4*)(out + (size_t)row * E_))[t] = o;
}

// ---------------- launch ---------------------------------------------------
extern "C" void kernel_launch(void* const* d_in, const int* in_sizes, int n_in,
                              void* d_out, int out_size)
{
    const float* xq    = (const float*)d_in[0];
    const float* xk    = (const float*)d_in[1];
    const float* xv    = (const float*)d_in[2];
    const unsigned char* mask = (const unsigned char*)d_in[3];
    const float* Wq = (const float*)d_in[4];
    const float* bq = (const float*)d_in[5];
    const float* Wk = (const float*)d_in[6];
    const float* bk = (const float*)d_in[7];
    const float* Wv = (const float*)d_in[8];
    const float* bv = (const float*)d_in[9];
    const float* Wo = (const float*)d_in[10];
    const float* bo = (const float*)d_in[11];
    const float* gamma = (const float*)d_in[12];
    const float* beta  = (const float*)d_in[13];
    float* out = (float*)d_out;

    __half *dQ, *dK, *dVT;
    float *dCTX, *dPROJ;
    cudaGetSymbolAddress((void**)&dQ,    g_Qh);
    cudaGetSymbolAddress((void**)&dK,    g_Kh);
    cudaGetSymbolAddress((void**)&dVT,   g_VTh);
    cudaGetSymbolAddress((void**)&dCTX,  g_CTX);
    cudaGetSymbolAddress((void**)&dPROJ, g_PROJ);

    cudaFuncSetAttribute(gemm_qkv,
                         cudaFuncAttributeMaxDynamicSharedMemorySize, GEMM_SMEM);
    cudaFuncSetAttribute(gemm_o,
                         cudaFuncAttributeMaxDynamicSharedMemorySize, GEMM_SMEM);
    cudaFuncSetAttribute(attn_tc,
                         cudaFuncAttributeMaxDynamicSharedMemorySize, ATTN_SMEM);

    gemm_qkv<<<dim3(E_ / BN, M_ / BM, 3), 256, GEMM_SMEM>>>(
        xq, Wq, bq, xk, Wk, bk, xv, Wv, bv, dQ, dK, dVT);

    attn_tc<<<dim3(L_ / 128, H_, B_), 128, ATTN_SMEM>>>(dQ, dK, dVT, mask, dCTX);

    gemm_o<<<dim3(E_ / BN, M_ / BM), 256, GEMM_SMEM>>>(dCTX, Wo, bo, xq, dPROJ);

    ln_kernel<<<M_, 256>>>(dPROJ, gamma, beta, out);
}

// round 15
// speedup vs baseline: 1.6829x; 1.2353x over previous
#include <cuda_runtime.h>
#include <cuda_fp16.h>
#include <math.h>
#include <stdint.h>

#define B_  2
#define L_  2048
#define E_  1024
#define H_  16
#define DH_ 64
#define M_  (B_*L_)

// fp16 GEMM tiling: 128x128 tile, BK=64, 2-stage cp.async
#define BK 64
#define GST 72               // smem k-stride in halves (64 + 8 pad)
#define GEMM_SMEM (2*2*128*GST*2)   // 73,728 B

// attention smem (fp16): 2 stages x (K + V^T) x 64 rows x 72 halves
#define KH_ST 72
#define ATTN_SMEM (2*2*64*KH_ST*2)   // 36,864 B

// ---------------- scratch (device globals; no allocation allowed) ----------
__device__ __half g_xqh[(size_t)M_*E_];
__device__ __half g_xkh[(size_t)M_*E_];
__device__ __half g_xvh[(size_t)M_*E_];
__device__ __half g_Wqh[(size_t)E_*E_];
__device__ __half g_Wkh[(size_t)E_*E_];
__device__ __half g_Wvh[(size_t)E_*E_];
__device__ __half g_Woh[(size_t)E_*E_];
__device__ __half g_Qh [(size_t)B_*H_*L_*DH_];
__device__ __half g_Kh [(size_t)B_*H_*L_*DH_];
__device__ __half g_VTh[(size_t)B_*H_*DH_*L_];   // [b,h,dh,l]
__device__ __half g_CTXh[(size_t)M_*E_];
__device__ float  g_PROJ[(size_t)M_*E_];

__device__ __forceinline__ void mma_f16(float c[4],
    uint32_t a0, uint32_t a1, uint32_t a2, uint32_t a3,
    uint32_t b0, uint32_t b1)
{
    asm volatile(
        "mma.sync.aligned.m16n8k16.row.col.f32.f16.f16.f32 "
        "{%0,%1,%2,%3}, {%4,%5,%6,%7}, {%8,%9}, {%0,%1,%2,%3};"
        : "+f"(c[0]), "+f"(c[1]), "+f"(c[2]), "+f"(c[3])
        : "r"(a0), "r"(a1), "r"(a2), "r"(a3), "r"(b0), "r"(b1));
}

// pack two fp32 into half2 {lo, hi} (first PTX source = high half)
__device__ __forceinline__ uint32_t f2h2(float lo, float hi) {
    uint32_t r;
    asm("cvt.rn.f16x2.f32 %0, %1, %2;" : "=r"(r) : "f"(hi), "f"(lo));
    return r;
}

__device__ __forceinline__ void cp16(uint32_t smem_addr, const void* gptr) {
    asm volatile("cp.async.cg.shared.global [%0], [%1], 16;"
                 :: "r"(smem_addr), "l"(gptr));
}
__device__ __forceinline__ void cp_commit() {
    asm volatile("cp.async.commit_group;");
}
__device__ __forceinline__ uint32_t s2u(const void* p) {
    return (uint32_t)__cvta_generic_to_shared(p);
}

// ---------------- fp32 -> fp16 conversion (z selects tensor) ---------------
__global__ __launch_bounds__(256) void f2h_kernel(
    const float* __restrict__ xq, const float* __restrict__ xk,
    const float* __restrict__ xv, const float* __restrict__ Wq,
    const float* __restrict__ Wk, const float* __restrict__ Wv,
    const float* __restrict__ Wo)
{
    const int z = blockIdx.z;
    const float* src;
    __half* dst;
    int n4;   // float4 count
    switch (z) {
        case 0: src = xq; dst = g_xqh; n4 = M_*E_/4; break;
        case 1: src = xk; dst = g_xkh; n4 = M_*E_/4; break;
        case 2: src = xv; dst = g_xvh; n4 = M_*E_/4; break;
        case 3: src = Wq; dst = g_Wqh; n4 = E_*E_/4; break;
        case 4: src = Wk; dst = g_Wkh; n4 = E_*E_/4; break;
        case 5: src = Wv; dst = g_Wvh; n4 = E_*E_/4; break;
        default: src = Wo; dst = g_Woh; n4 = E_*E_/4; break;
    }
    const int i = blockIdx.x * 256 + threadIdx.x;
    if (i < n4) {
        const float4 v = ((const float4*)src)[i];
        uint2 o;
        o.x = f2h2(v.x, v.y);
        o.y = f2h2(v.z, v.w);
        ((uint2*)dst)[i] = o;
    }
}

// ---------------- fp16 GEMM body, 2-stage cp.async --------------------------
// out = A[M,K] @ W[N,K]^T + bias
// MODE 0: half scatter [B,H,L,DH];  MODE 2: half scatter transposed [B,H,DH,L]
// MODE 1: fp32 [M,N] + resid
template<int MODE>
__device__ __forceinline__ void gemm_body(
    const __half* __restrict__ A, const __half* __restrict__ W,
    const float* __restrict__ bias, const float* __restrict__ resid,
    void* __restrict__ outv)
{
    extern __shared__ __half gsm[];
    __half* sA = gsm;                    // [2][128][GST]
    __half* sB = gsm + 2*128*GST;        // [2][128][GST]

    const int t    = threadIdx.x;
    const int m0   = blockIdx.y << 7;
    const int n0   = blockIdx.x << 7;
    const int wid  = t >> 5, lane = t & 31;
    const int wm   = wid >> 2;
    const int wn   = wid & 3;
    const int grp  = lane >> 2;
    const int qd   = lane & 3;

    auto issue = [&](int k0, int buf) {
        #pragma unroll
        for (int i = 0; i < 4; i++) {
            const int idx = t + (i << 8);
            const int row = idx >> 3, ch = (idx & 7) << 3;   // 8 halves = 16B
            cp16(s2u(sA + (size_t)(buf * 128 + row) * GST + ch),
                 A + (size_t)(m0 + row) * E_ + k0 + ch);
            cp16(s2u(sB + (size_t)(buf * 128 + row) * GST + ch),
                 W + (size_t)(n0 + row) * E_ + k0 + ch);
        }
        cp_commit();
    };

    float c[4][4][4];
    #pragma unroll
    for (int mt = 0; mt < 4; mt++)
        #pragma unroll
        for (int nt = 0; nt < 4; nt++)
            #pragma unroll
            for (int r = 0; r < 4; r++) c[mt][nt][r] = 0.f;

    issue(0, 0);
    const int NK = E_ / BK;    // 16
    for (int kt = 0; kt < NK; kt++) {
        const int cur = kt & 1;
        if (kt + 1 < NK) {
            issue((kt + 1) * BK, cur ^ 1);
            asm volatile("cp.async.wait_group 1;");
        } else {
            asm volatile("cp.async.wait_group 0;");
        }
        __syncthreads();

        const __half* cA = sA + (size_t)cur * 128 * GST;
        const __half* cB = sB + (size_t)cur * 128 * GST;

        #pragma unroll
        for (int ks = 0; ks < 4; ks++) {
            const int kc = (ks << 4) + (qd << 1);
            uint32_t a[4][4], b[4][2];
            #pragma unroll
            for (int mt = 0; mt < 4; mt++) {
                const __half* ar = cA + ((wm << 6) + (mt << 4) + grp) * GST + kc;
                a[mt][0] = *(const uint32_t*)(ar);
                a[mt][1] = *(const uint32_t*)(ar + (GST << 3));   // +8 rows
                a[mt][2] = *(const uint32_t*)(ar + 8);
                a[mt][3] = *(const uint32_t*)(ar + (GST << 3) + 8);
            }
            #pragma unroll
            for (int nt = 0; nt < 4; nt++) {
                const __half* br = cB + ((wn << 5) + (nt << 3) + grp) * GST + kc;
                b[nt][0] = *(const uint32_t*)(br);
                b[nt][1] = *(const uint32_t*)(br + 8);
            }
            #pragma unroll
            for (int mt = 0; mt < 4; mt++)
                #pragma unroll
                for (int nt = 0; nt < 4; nt++)
                    mma_f16(c[mt][nt], a[mt][0], a[mt][1], a[mt][2], a[mt][3],
                            b[nt][0], b[nt][1]);
        }
        __syncthreads();
    }

    #pragma unroll
    for (int mt = 0; mt < 4; mt++) {
        #pragma unroll
        for (int half = 0; half < 2; half++) {
            const int m = m0 + (wm << 6) + (mt << 4) + grp + (half << 3);
            #pragma unroll
            for (int nt = 0; nt < 4; nt++) {
                const int n = n0 + (wn << 5) + (nt << 3) + (qd << 1);
                const float2 bv = *(const float2*)(bias + n);
                float v0 = c[mt][nt][half * 2 + 0] + bv.x;
                float v1 = c[mt][nt][half * 2 + 1] + bv.y;
                if (MODE == 1) {
                    float* o = (float*)outv;
                    const size_t idx = (size_t)m * E_ + n;
                    const float2 rv = *(const float2*)(resid + idx);
                    float2 ov; ov.x = v0 + rv.x; ov.y = v1 + rv.y;
                    *(float2*)(o + idx) = ov;
                } else if (MODE == 0) {
                    __half* o = (__half*)outv;
                    const int b = m >> 11;
                    const int l = m & (L_ - 1);
                    const int h = n >> 6;
                    const int d = n & 63;
                    *(uint32_t*)(o + (((((size_t)b * H_ + h) << 11) + l) << 6) + d) =
                        f2h2(v0, v1);
                } else {
                    __half* o = (__half*)outv;    // V^T: [b,h,dh,l]
                    const int b = m >> 11;
                    const int l = m & (L_ - 1);
                    const int h = n >> 6;
                    const int d = n & 63;
                    const size_t base = (((size_t)b * H_ + h) * DH_ + d) * L_ + l;
                    o[base]      = __float2half_rn(v0);
                    o[base + L_] = __float2half_rn(v1);   // d+1
                }
            }
        }
    }
}

// fused QKV projection: blockIdx.z selects {q,k,v}
__global__ __launch_bounds__(256, 2) void gemm_qkv(
    __half* __restrict__ dQ, __half* __restrict__ dK, __half* __restrict__ dVT,
    const float* __restrict__ bq, const float* __restrict__ bk,
    const float* __restrict__ bv)
{
    const int z = blockIdx.z;
    if (z == 0)      gemm_body<0>(g_xqh, g_Wqh, bq, nullptr, dQ);
    else if (z == 1) gemm_body<0>(g_xkh, g_Wkh, bk, nullptr, dK);
    else             gemm_body<2>(g_xvh, g_Wvh, bv, nullptr, dVT);
}

__global__ __launch_bounds__(256, 2) void gemm_o(
    const float* __restrict__ bias, const float* __restrict__ resid,
    float* __restrict__ out)
{
    gemm_body<1>(g_CTXh, g_Woh, bias, resid, out);
}

// ---------------- fp16 tensor-core flash attention --------------------------
// grid (L/128, H, B), block 128 (4 warps). Warp owns 32 q-rows (2 m-tiles).
__global__ __launch_bounds__(128, 2) void attn_tc(
    const __half* __restrict__ Qg, const __half* __restrict__ Kg,
    const __half* __restrict__ VTg, const unsigned char* __restrict__ mask,
    __half* __restrict__ CTX)
{
    extern __shared__ __half smh[];
    __half* sKb = smh;                   // [2][64*KH_ST]
    __half* sVb = smh + 2 * 64 * KH_ST;  // [2][64*KH_ST]  (V^T: rows=dh, cols=key)

    const int t    = threadIdx.x;
    const int lane = t & 31, wid = t >> 5;
    const int grp  = lane >> 2, qd = lane & 3;
    const int qbase = wid << 5;             // 32 rows per warp
    const int qt = blockIdx.x, h = blockIdx.y, b = blockIdx.z;

    const __half* Qb  = Qg  + (((size_t)b * H_ + h) * L_ + (qt << 7)) * DH_;
    const __half* Kb  = Kg  + ((size_t)b * H_ + h) * L_ * DH_;
    const __half* VTb = VTg + ((size_t)b * H_ + h) * DH_ * L_;

    // Q fragments -> registers (half2-packed)
    uint32_t qA[2][4][4];
    #pragma unroll
    for (int mt = 0; mt < 2; mt++) {
        const __half* q0 = Qb + (size_t)(qbase + (mt << 4) + grp) * DH_;
        #pragma unroll
        for (int ks = 0; ks < 4; ks++) {
            const int kc = (ks << 4) + (qd << 1);
            qA[mt][ks][0] = *(const uint32_t*)(q0 + kc);
            qA[mt][ks][1] = *(const uint32_t*)(q0 + (DH_ << 3) + kc);
            qA[mt][ks][2] = *(const uint32_t*)(q0 + kc + 8);
            qA[mt][ks][3] = *(const uint32_t*)(q0 + (DH_ << 3) + kc + 8);
        }
    }

    float accO[2][8][4];
    #pragma unroll
    for (int mt = 0; mt < 2; mt++)
        #pragma unroll
        for (int nt = 0; nt < 8; nt++)
            #pragma unroll
            for (int r = 0; r < 4; r++) accO[mt][nt][r] = 0.f;
    float mrun[2][2], lrun[2][2];
    #pragma unroll
    for (int mt = 0; mt < 2; mt++) {
        mrun[mt][0] = -1e30f; mrun[mt][1] = -1e30f;
        lrun[mt][0] = 0.f;    lrun[mt][1] = 0.f;
    }

    const int qrow = (qt << 7) + qbase + grp;
    const unsigned char* mbase = mask + ((size_t)b * L_ + qrow) * L_;

    auto issueKV = [&](int kt, int buf) {
        const __half* Kt = Kb + ((size_t)kt << 6) * DH_;
        const __half* Vt = VTb + (kt << 6);
        __half* dK = sKb + buf * 64 * KH_ST;
        __half* dV = sVb + buf * 64 * KH_ST;
        #pragma unroll
        for (int i = 0; i < 4; i++) {
            const int idx = t + (i << 7);
            const int row = idx >> 3, ch = (idx & 7) << 3;
            cp16(s2u(dK + row * KH_ST + ch), Kt + (row << 6) + ch);
            cp16(s2u(dV + row * KH_ST + ch), Vt + (size_t)row * L_ + ch);
        }
        cp_commit();
    };

    issueKV(0, 0);

    const int NT = L_ / 64;   // 32
    for (int kt = 0; kt < NT; kt++) {
        const int cur = kt & 1;
        if (kt + 1 < NT) issueKV(kt + 1, cur ^ 1);

        // prefetch mask bytes for this tile
        uchar2 mk[2][2][8];
        const int colb = (kt << 6) + (qd << 1);
        #pragma unroll
        for (int mt = 0; mt < 2; mt++)
            #pragma unroll
            for (int hf = 0; hf < 2; hf++) {
                const unsigned char* mp =
                    mbase + (size_t)((mt << 4) + (hf << 3)) * L_ + colb;
                #pragma unroll
                for (int nt = 0; nt < 8; nt++)
                    mk[mt][hf][nt] = *(const uchar2*)(mp + (nt << 3));
            }

        if (kt + 1 < NT) asm volatile("cp.async.wait_group 1;");
        else             asm volatile("cp.async.wait_group 0;");
        __syncthreads();

        const __half* K = sKb + cur * 64 * KH_ST;
        const __half* V = sVb + cur * 64 * KH_ST;

        // ---- S = Q K^T ----
        float s[2][8][4];
        #pragma unroll
        for (int mt = 0; mt < 2; mt++)
            #pragma unroll
            for (int nt = 0; nt < 8; nt++)
                #pragma unroll
                for (int r = 0; r < 4; r++) s[mt][nt][r] = 0.f;

        #pragma unroll
        for (int ks = 0; ks < 4; ks++) {
            const int kc = (ks << 4) + (qd << 1);
            #pragma unroll
            for (int nt = 0; nt < 8; nt++) {
                const __half* kr = K + ((nt << 3) + grp) * KH_ST + kc;
                const uint32_t b0 = *(const uint32_t*)(kr);
                const uint32_t b1 = *(const uint32_t*)(kr + 8);
                mma_f16(s[0][nt], qA[0][ks][0], qA[0][ks][1], qA[0][ks][2], qA[0][ks][3], b0, b1);
                mma_f16(s[1][nt], qA[1][ks][0], qA[1][ks][1], qA[1][ks][2], qA[1][ks][3], b0, b1);
            }
        }

        // ---- scale + mask + online softmax per m-tile ----
        #pragma unroll
        for (int mt = 0; mt < 2; mt++) {
            #pragma unroll
            for (int nt = 0; nt < 8; nt++) {
                s[mt][nt][0] = mk[mt][0][nt].x ? -1e30f : s[mt][nt][0] * 0.125f;
                s[mt][nt][1] = mk[mt][0][nt].y ? -1e30f : s[mt][nt][1] * 0.125f;
                s[mt][nt][2] = mk[mt][1][nt].x ? -1e30f : s[mt][nt][2] * 0.125f;
                s[mt][nt][3] = mk[mt][1][nt].y ? -1e30f : s[mt][nt][3] * 0.125f;
            }
            float mlo = -1e30f, mhi = -1e30f;
            #pragma unroll
            for (int nt = 0; nt < 8; nt++) {
                mlo = fmaxf(mlo, fmaxf(s[mt][nt][0], s[mt][nt][1]));
                mhi = fmaxf(mhi, fmaxf(s[mt][nt][2], s[mt][nt][3]));
            }
            mlo = fmaxf(mlo, __shfl_xor_sync(0xffffffffu, mlo, 1));
            mlo = fmaxf(mlo, __shfl_xor_sync(0xffffffffu, mlo, 2));
            mhi = fmaxf(mhi, __shfl_xor_sync(0xffffffffu, mhi, 1));
            mhi = fmaxf(mhi, __shfl_xor_sync(0xffffffffu, mhi, 2));

            const float mn0 = fmaxf(mrun[mt][0], mlo);
            const float mn1 = fmaxf(mrun[mt][1], mhi);
            const float al0 = __expf(mrun[mt][0] - mn0);
            const float al1 = __expf(mrun[mt][1] - mn1);
            mrun[mt][0] = mn0; mrun[mt][1] = mn1;

            float rs0 = 0.f, rs1 = 0.f;
            #pragma unroll
            for (int nt = 0; nt < 8; nt++) {
                s[mt][nt][0] = __expf(s[mt][nt][0] - mn0);
                s[mt][nt][1] = __expf(s[mt][nt][1] - mn0);
                s[mt][nt][2] = __expf(s[mt][nt][2] - mn1);
                s[mt][nt][3] = __expf(s[mt][nt][3] - mn1);
                rs0 += s[mt][nt][0] + s[mt][nt][1];
                rs1 += s[mt][nt][2] + s[mt][nt][3];
            }
            rs0 += __shfl_xor_sync(0xffffffffu, rs0, 1);
            rs0 += __shfl_xor_sync(0xffffffffu, rs0, 2);
            rs1 += __shfl_xor_sync(0xffffffffu, rs1, 1);
            rs1 += __shfl_xor_sync(0xffffffffu, rs1, 2);
            lrun[mt][0] = lrun[mt][0] * al0 + rs0;
            lrun[mt][1] = lrun[mt][1] * al1 + rs1;

            #pragma unroll
            for (int nt = 0; nt < 8; nt++) {
                accO[mt][nt][0] *= al0; accO[mt][nt][1] *= al0;
                accO[mt][nt][2] *= al1; accO[mt][nt][3] *= al1;
            }
        }

        // ---- O += P V : P frag register-resident ----
        #pragma unroll
        for (int kc = 0; kc < 4; kc++) {
            uint32_t pa[2][4];
            #pragma unroll
            for (int mt = 0; mt < 2; mt++) {
                pa[mt][0] = f2h2(s[mt][2*kc  ][0], s[mt][2*kc  ][1]);
                pa[mt][1] = f2h2(s[mt][2*kc  ][2], s[mt][2*kc  ][3]);
                pa[mt][2] = f2h2(s[mt][2*kc+1][0], s[mt][2*kc+1][1]);
                pa[mt][3] = f2h2(s[mt][2*kc+1][2], s[mt][2*kc+1][3]);
            }
            const int kcol = (kc << 4) + (qd << 1);
            #pragma unroll
            for (int nt = 0; nt < 8; nt++) {
                const __half* vr = V + ((nt << 3) + grp) * KH_ST + kcol;
                const uint32_t b0 = *(const uint32_t*)(vr);
                const uint32_t b1 = *(const uint32_t*)(vr + 8);
                mma_f16(accO[0][nt], pa[0][0], pa[0][1], pa[0][2], pa[0][3], b0, b1);
                mma_f16(accO[1][nt], pa[1][0], pa[1][1], pa[1][2], pa[1][3], b0, b1);
            }
        }
        __syncthreads();
    }

    // ---- epilogue: write CTX in fp16 ----
    #pragma unroll
    for (int mt = 0; mt < 2; mt++) {
        const float inv0 = 1.0f / lrun[mt][0];
        const float inv1 = 1.0f / lrun[mt][1];
        __half* Cp = CTX + ((size_t)b * L_ + qrow + (mt << 4)) * E_ + (h << 6);
        #pragma unroll
        for (int nt = 0; nt < 8; nt++) {
            const int col = (nt << 3) + (qd << 1);
            *(uint32_t*)(Cp + col) =
                f2h2(accO[mt][nt][0] * inv0, accO[mt][nt][1] * inv0);
            *(uint32_t*)(Cp + (size_t)8 * E_ + col) =
                f2h2(accO[mt][nt][2] * inv1, accO[mt][nt][3] * inv1);
        }
    }
}

// ---------------- LayerNorm over E=1024, one row per block -----------------
__global__ __launch_bounds__(256) void ln_kernel(
    const float* __restrict__ X, const float* __restrict__ gamma,
    const float* __restrict__ beta, float* __restrict__ out)
{
    __shared__ float red[8];
    __shared__ float s_mu, s_rstd;
    const int row = blockIdx.x;
    const int t = threadIdx.x;

    float4 v = ((const float4*)(X + (size_t)row * E_))[t];
    float s = v.x + v.y + v.z + v.w;
    #pragma unroll
    for (int off = 16; off >= 1; off >>= 1) s += __shfl_xor_sync(0xffffffffu, s, off);
    if ((t & 31) == 0) red[t >> 5] = s;
    __syncthreads();
    if (t == 0) {
        float tot = 0.f;
        #pragma unroll
        for (int k = 0; k < 8; k++) tot += red[k];
        s_mu = tot * (1.0f / E_);
    }
    __syncthreads();
    const float mu = s_mu;

    float dx = v.x - mu, dy = v.y - mu, dz = v.z - mu, dw = v.w - mu;
    float sq = dx * dx + dy * dy + dz * dz + dw * dw;
    #pragma unroll
    for (int off = 16; off >= 1; off >>= 1) sq += __shfl_xor_sync(0xffffffffu, sq, off);
    __syncthreads();
    if ((t & 31) == 0) red[t >> 5] = sq;
    __syncthreads();
    if (t == 0) {
        float tot = 0.f;
        #pragma unroll
        for (int k = 0; k < 8; k++) tot += red[k];
        s_rstd = rsqrtf(tot * (1.0f / E_) + 1e-6f);
    }
    __syncthreads();
    const float rstd = s_rstd;

    float4 g  = ((const float4*)gamma)[t];
    float4 be = ((const float4*)beta)[t];
    float4 o;
    o.x = dx * rstd * g.x + be.x;
    o.y = dy * rstd * g.y + be.y;
    o.z = dz * rstd * g.z + be.z;
    o.w = dw * rstd * g.w + be.w;
    ((float4*)(out + (size_t)row * E_))[t] = o;
}

// ---------------- launch ---------------------------------------------------
extern "C" void kernel_launch(void* const* d_in, const int* in_sizes, int n_in,
                              void* d_out, int out_size)
{
    const float* xq    = (const float*)d_in[0];
    const float* xk    = (const float*)d_in[1];
    const float* xv    = (const float*)d_in[2];
    const unsigned char* mask = (const unsigned char*)d_in[3];
    const float* Wq = (const float*)d_in[4];
    const float* bq = (const float*)d_in[5];
    const float* Wk = (const float*)d_in[6];
    const float* bk = (const float*)d_in[7];
    const float* Wv = (const float*)d_in[8];
    const float* bv = (const float*)d_in[9];
    const float* Wo = (const float*)d_in[10];
    const float* bo = (const float*)d_in[11];
    const float* gamma = (const float*)d_in[12];
    const float* beta  = (const float*)d_in[13];
    float* out = (float*)d_out;

    __half *dQ, *dK, *dVT, *dCTX;
    float *dPROJ;
    cudaGetSymbolAddress((void**)&dQ,    g_Qh);
    cudaGetSymbolAddress((void**)&dK,    g_Kh);
    cudaGetSymbolAddress((void**)&dVT,   g_VTh);
    cudaGetSymbolAddress((void**)&dCTX,  g_CTXh);
    cudaGetSymbolAddress((void**)&dPROJ, g_PROJ);

    cudaFuncSetAttribute(gemm_qkv,
                         cudaFuncAttributeMaxDynamicSharedMemorySize, GEMM_SMEM);
    cudaFuncSetAttribute(gemm_o,
                         cudaFuncAttributeMaxDynamicSharedMemorySize, GEMM_SMEM);
    cudaFuncSetAttribute(attn_tc,
                         cudaFuncAttributeMaxDynamicSharedMemorySize, ATTN_SMEM);

    // fp32 -> fp16 conversion (x inputs + weights)
    f2h_kernel<<<dim3((M_*E_/4 + 255)/256, 1, 7), 256>>>(
        xq, xk, xv, Wq, Wk, Wv, Wo);

    gemm_qkv<<<dim3(E_ / 128, M_ / 128, 3), 256, GEMM_SMEM>>>(
        dQ, dK, dVT, bq, bk, bv);

    attn_tc<<<dim3(L_ / 128, H_, B_), 128, ATTN_SMEM>>>(dQ, dK, dVT, mask, dCTX);

    gemm_o<<<dim3(E_ / 128, M_ / 128), 256, GEMM_SMEM>>>(bo, xq, dPROJ);

    ln_kernel<<<M_, 256>>>(dPROJ, gamma, beta, out);
}

// round 16
// speedup vs baseline: 1.7764x; 1.0556x over previous
#include <cuda_runtime.h>
#include <cuda_fp16.h>
#include <math.h>
#include <stdint.h>

#define B_  2
#define L_  2048
#define E_  1024
#define H_  16
#define DH_ 64
#define M_  (B_*L_)

// fp16 GEMM tiling: 128x128 tile, BK=64, 2-stage cp.async
#define BK 64
#define GST 72               // smem k-stride in halves (64 + 8 pad; 144B = 9*16B)
#define GEMM_SMEM (2*2*128*GST*2)   // 73,728 B

// attention smem (fp16): 2 stages x (K + V) x 64 rows x 72 halves
#define KH_ST 72
#define ATTN_SMEM (2*2*64*KH_ST*2)   // 36,864 B

// ---------------- scratch (device globals; no allocation allowed) ----------
__device__ __half g_xqh[(size_t)M_*E_];
__device__ __half g_xkh[(size_t)M_*E_];
__device__ __half g_xvh[(size_t)M_*E_];
__device__ __half g_Wqh[(size_t)E_*E_];
__device__ __half g_Wkh[(size_t)E_*E_];
__device__ __half g_Wvh[(size_t)E_*E_];
__device__ __half g_Woh[(size_t)E_*E_];
__device__ __half g_Qh [(size_t)B_*H_*L_*DH_];
__device__ __half g_Kh [(size_t)B_*H_*L_*DH_];
__device__ __half g_Vh [(size_t)B_*H_*L_*DH_];   // [b,h,l,dh] (like K)
__device__ __half g_CTXh[(size_t)M_*E_];
__device__ float  g_PROJ[(size_t)M_*E_];

__device__ __forceinline__ void mma_f16(float c[4],
    uint32_t a0, uint32_t a1, uint32_t a2, uint32_t a3,
    uint32_t b0, uint32_t b1)
{
    asm volatile(
        "mma.sync.aligned.m16n8k16.row.col.f32.f16.f16.f32 "
        "{%0,%1,%2,%3}, {%4,%5,%6,%7}, {%8,%9}, {%0,%1,%2,%3};"
        : "+f"(c[0]), "+f"(c[1]), "+f"(c[2]), "+f"(c[3])
        : "r"(a0), "r"(a1), "r"(a2), "r"(a3), "r"(b0), "r"(b1));
}

#define LDSM_X4(r0,r1,r2,r3,addr) \
    asm volatile("ldmatrix.sync.aligned.m8n8.x4.shared.b16 {%0,%1,%2,%3}, [%4];" \
        : "=r"(r0),"=r"(r1),"=r"(r2),"=r"(r3) : "r"(addr))
#define LDSM_X4_T(r0,r1,r2,r3,addr) \
    asm volatile("ldmatrix.sync.aligned.m8n8.x4.trans.shared.b16 {%0,%1,%2,%3}, [%4];" \
        : "=r"(r0),"=r"(r1),"=r"(r2),"=r"(r3) : "r"(addr))

// pack two fp32 into half2 {lo, hi} (first PTX source = high half)
__device__ __forceinline__ uint32_t f2h2(float lo, float hi) {
    uint32_t r;
    asm("cvt.rn.f16x2.f32 %0, %1, %2;" : "=r"(r) : "f"(hi), "f"(lo));
    return r;
}

__device__ __forceinline__ void cp16(uint32_t smem_addr, const void* gptr) {
    asm volatile("cp.async.cg.shared.global [%0], [%1], 16;"
                 :: "r"(smem_addr), "l"(gptr));
}
__device__ __forceinline__ void cp_commit() {
    asm volatile("cp.async.commit_group;");
}
__device__ __forceinline__ uint32_t s2u(const void* p) {
    return (uint32_t)__cvta_generic_to_shared(p);
}

// ---------------- fp32 -> fp16 conversion (z selects tensor) ---------------
__global__ __launch_bounds__(256) void f2h_kernel(
    const float* __restrict__ xq, const float* __restrict__ xk,
    const float* __restrict__ xv, const float* __restrict__ Wq,
    const float* __restrict__ Wk, const float* __restrict__ Wv,
    const float* __restrict__ Wo)
{
    const int z = blockIdx.z;
    const float* src;
    __half* dst;
    int n4;
    switch (z) {
        case 0: src = xq; dst = g_xqh; n4 = M_*E_/4; break;
        case 1: src = xk; dst = g_xkh; n4 = M_*E_/4; break;
        case 2: src = xv; dst = g_xvh; n4 = M_*E_/4; break;
        case 3: src = Wq; dst = g_Wqh; n4 = E_*E_/4; break;
        case 4: src = Wk; dst = g_Wkh; n4 = E_*E_/4; break;
        case 5: src = Wv; dst = g_Wvh; n4 = E_*E_/4; break;
        default: src = Wo; dst = g_Woh; n4 = E_*E_/4; break;
    }
    const int i = blockIdx.x * 256 + threadIdx.x;
    if (i < n4) {
        const float4 v = ((const float4*)src)[i];
        uint2 o;
        o.x = f2h2(v.x, v.y);
        o.y = f2h2(v.z, v.w);
        ((uint2*)dst)[i] = o;
    }
}

// ---------------- fp16 GEMM body, 2-stage cp.async + ldmatrix --------------
// out = A[M,K] @ W[N,K]^T + bias
// MODE 0: half scatter [B,H,L,DH];  MODE 1: fp32 [M,N] + resid
template<int MODE>
__device__ __forceinline__ void gemm_body(
    const __half* __restrict__ A, const __half* __restrict__ W,
    const float* __restrict__ bias, const float* __restrict__ resid,
    void* __restrict__ outv)
{
    extern __shared__ __half gsm[];
    __half* sA = gsm;                    // [2][128][GST]
    __half* sB = gsm + 2*128*GST;        // [2][128][GST]

    const int t    = threadIdx.x;
    const int m0   = blockIdx.y << 7;
    const int n0   = blockIdx.x << 7;
    const int wid  = t >> 5, lane = t & 31;
    const int wm   = wid >> 2;
    const int wn   = wid & 3;
    const int grp  = lane >> 2;
    const int qd   = lane & 3;

    // ldmatrix lane address patterns
    const int rAp = (lane & 7) + ((lane >> 3) & 1) * 8;   // A-frag row off
    const int cAp = (lane >> 4) << 3;                     // A-frag col off
    const int rBp = (lane & 7) + (lane >> 4) * 8;         // B-frag row off
    const int cBp = ((lane >> 3) & 1) << 3;               // B-frag col off

    auto issue = [&](int k0, int buf) {
        #pragma unroll
        for (int i = 0; i < 4; i++) {
            const int idx = t + (i << 8);
            const int row = idx >> 3, ch = (idx & 7) << 3;
            cp16(s2u(sA + (size_t)(buf * 128 + row) * GST + ch),
                 A + (size_t)(m0 + row) * E_ + k0 + ch);
            cp16(s2u(sB + (size_t)(buf * 128 + row) * GST + ch),
                 W + (size_t)(n0 + row) * E_ + k0 + ch);
        }
        cp_commit();
    };

    float c[4][4][4];
    #pragma unroll
    for (int mt = 0; mt < 4; mt++)
        #pragma unroll
        for (int nt = 0; nt < 4; nt++)
            #pragma unroll
            for (int r = 0; r < 4; r++) c[mt][nt][r] = 0.f;

    issue(0, 0);
    const int NK = E_ / BK;    // 16
    for (int kt = 0; kt < NK; kt++) {
        const int cur = kt & 1;
        if (kt + 1 < NK) {
            issue((kt + 1) * BK, cur ^ 1);
            asm volatile("cp.async.wait_group 1;");
        } else {
            asm volatile("cp.async.wait_group 0;");
        }
        __syncthreads();

        const __half* cA = sA + (size_t)cur * 128 * GST;
        const __half* cB = sB + (size_t)cur * 128 * GST;

        #pragma unroll
        for (int ks = 0; ks < 4; ks++) {
            const int kc16 = ks << 4;
            uint32_t a[4][4], b[4][2];
            #pragma unroll
            for (int mt = 0; mt < 4; mt++) {
                const uint32_t ad = s2u(cA +
                    ((wm << 6) + (mt << 4) + rAp) * GST + kc16 + cAp);
                LDSM_X4(a[mt][0], a[mt][1], a[mt][2], a[mt][3], ad);
            }
            #pragma unroll
            for (int j = 0; j < 2; j++) {
                const uint32_t ad = s2u(cB +
                    ((wn << 5) + (j << 4) + rBp) * GST + kc16 + cBp);
                LDSM_X4(b[2*j][0], b[2*j][1], b[2*j+1][0], b[2*j+1][1], ad);
            }
            #pragma unroll
            for (int mt = 0; mt < 4; mt++)
                #pragma unroll
                for (int nt = 0; nt < 4; nt++)
                    mma_f16(c[mt][nt], a[mt][0], a[mt][1], a[mt][2], a[mt][3],
                            b[nt][0], b[nt][1]);
        }
        __syncthreads();
    }

    #pragma unroll
    for (int mt = 0; mt < 4; mt++) {
        #pragma unroll
        for (int half = 0; half < 2; half++) {
            const int m = m0 + (wm << 6) + (mt << 4) + grp + (half << 3);
            #pragma unroll
            for (int nt = 0; nt < 4; nt++) {
                const int n = n0 + (wn << 5) + (nt << 3) + (qd << 1);
                const float2 bv = *(const float2*)(bias + n);
                float v0 = c[mt][nt][half * 2 + 0] + bv.x;
                float v1 = c[mt][nt][half * 2 + 1] + bv.y;
                if (MODE == 1) {
                    float* o = (float*)outv;
                    const size_t idx = (size_t)m * E_ + n;
                    const float2 rv = *(const float2*)(resid + idx);
                    float2 ov; ov.x = v0 + rv.x; ov.y = v1 + rv.y;
                    *(float2*)(o + idx) = ov;
                } else {
                    __half* o = (__half*)outv;
                    const int b = m >> 11;
                    const int l = m & (L_ - 1);
                    const int h = n >> 6;
                    const int d = n & 63;
                    *(uint32_t*)(o + (((((size_t)b * H_ + h) << 11) + l) << 6) + d) =
                        f2h2(v0, v1);
                }
            }
        }
    }
}

// fused QKV projection: blockIdx.z selects {q,k,v}
__global__ __launch_bounds__(256, 2) void gemm_qkv(
    __half* __restrict__ dQ, __half* __restrict__ dK, __half* __restrict__ dV,
    const float* __restrict__ bq, const float* __restrict__ bk,
    const float* __restrict__ bv)
{
    const int z = blockIdx.z;
    if (z == 0)      gemm_body<0>(g_xqh, g_Wqh, bq, nullptr, dQ);
    else if (z == 1) gemm_body<0>(g_xkh, g_Wkh, bk, nullptr, dK);
    else             gemm_body<0>(g_xvh, g_Wvh, bv, nullptr, dV);
}

__global__ __launch_bounds__(256, 2) void gemm_o(
    const float* __restrict__ bias, const float* __restrict__ resid,
    float* __restrict__ out)
{
    gemm_body<1>(g_CTXh, g_Woh, bias, resid, out);
}

// ---------------- fp16 flash attention with ldmatrix ------------------------
// grid (L/128, H, B), block 128 (4 warps). Warp owns 32 q-rows (2 m-tiles).
__global__ __launch_bounds__(128, 2) void attn_tc(
    const __half* __restrict__ Qg, const __half* __restrict__ Kg,
    const __half* __restrict__ Vg, const unsigned char* __restrict__ mask,
    __half* __restrict__ CTX)
{
    extern __shared__ __half smh[];
    __half* sKb = smh;                   // [2][64*KH_ST]
    __half* sVb = smh + 2 * 64 * KH_ST;  // [2][64*KH_ST]  (V: rows=key, cols=dh)

    const int t    = threadIdx.x;
    const int lane = t & 31, wid = t >> 5;
    const int grp  = lane >> 2, qd = lane & 3;
    const int qbase = wid << 5;
    const int qt = blockIdx.x, h = blockIdx.y, b = blockIdx.z;

    const int rAp = (lane & 7) + ((lane >> 3) & 1) * 8;   // trans-V pattern
    const int cAp = (lane >> 4) << 3;
    const int rBp = (lane & 7) + (lane >> 4) * 8;         // K B-frag pattern
    const int cBp = ((lane >> 3) & 1) << 3;

    const __half* Qb = Qg + (((size_t)b * H_ + h) * L_ + (qt << 7)) * DH_;
    const __half* Kb = Kg + ((size_t)b * H_ + h) * L_ * DH_;
    const __half* Vb = Vg + ((size_t)b * H_ + h) * L_ * DH_;

    // Q fragments -> registers (half2-packed)
    uint32_t qA[2][4][4];
    #pragma unroll
    for (int mt = 0; mt < 2; mt++) {
        const __half* q0 = Qb + (size_t)(qbase + (mt << 4) + grp) * DH_;
        #pragma unroll
        for (int ks = 0; ks < 4; ks++) {
            const int kc = (ks << 4) + (qd << 1);
            qA[mt][ks][0] = *(const uint32_t*)(q0 + kc);
            qA[mt][ks][1] = *(const uint32_t*)(q0 + (DH_ << 3) + kc);
            qA[mt][ks][2] = *(const uint32_t*)(q0 + kc + 8);
            qA[mt][ks][3] = *(const uint32_t*)(q0 + (DH_ << 3) + kc + 8);
        }
    }

    float accO[2][8][4];
    #pragma unroll
    for (int mt = 0; mt < 2; mt++)
        #pragma unroll
        for (int nt = 0; nt < 8; nt++)
            #pragma unroll
            for (int r = 0; r < 4; r++) accO[mt][nt][r] = 0.f;
    float mrun[2][2], lrun[2][2];
    #pragma unroll
    for (int mt = 0; mt < 2; mt++) {
        mrun[mt][0] = -1e30f; mrun[mt][1] = -1e30f;
        lrun[mt][0] = 0.f;    lrun[mt][1] = 0.f;
    }

    const int qrow = (qt << 7) + qbase + grp;
    const unsigned char* mbase = mask + ((size_t)b * L_ + qrow) * L_;

    auto issueKV = [&](int kt, int buf) {
        const __half* Kt = Kb + ((size_t)kt << 6) * DH_;
        const __half* Vt = Vb + ((size_t)kt << 6) * DH_;
        __half* dK = sKb + buf * 64 * KH_ST;
        __half* dV = sVb + buf * 64 * KH_ST;
        #pragma unroll
        for (int i = 0; i < 4; i++) {
            const int idx = t + (i << 7);
            const int row = idx >> 3, ch = (idx & 7) << 3;
            cp16(s2u(dK + row * KH_ST + ch), Kt + (row << 6) + ch);
            cp16(s2u(dV + row * KH_ST + ch), Vt + (row << 6) + ch);
        }
        cp_commit();
    };

    issueKV(0, 0);

    const int NT = L_ / 64;   // 32
    for (int kt = 0; kt < NT; kt++) {
        const int cur = kt & 1;
        if (kt + 1 < NT) issueKV(kt + 1, cur ^ 1);

        // prefetch mask bytes for this tile
        uchar2 mk[2][2][8];
        const int colb = (kt << 6) + (qd << 1);
        #pragma unroll
        for (int mt = 0; mt < 2; mt++)
            #pragma unroll
            for (int hf = 0; hf < 2; hf++) {
                const unsigned char* mp =
                    mbase + (size_t)((mt << 4) + (hf << 3)) * L_ + colb;
                #pragma unroll
                for (int nt = 0; nt < 8; nt++)
                    mk[mt][hf][nt] = *(const uchar2*)(mp + (nt << 3));
            }

        if (kt + 1 < NT) asm volatile("cp.async.wait_group 1;");
        else             asm volatile("cp.async.wait_group 0;");
        __syncthreads();

        const __half* K = sKb + cur * 64 * KH_ST;
        const __half* V = sVb + cur * 64 * KH_ST;

        // ---- S = Q K^T (ldmatrix B-frags, 2 nt per op) ----
        float s[2][8][4];
        #pragma unroll
        for (int mt = 0; mt < 2; mt++)
            #pragma unroll
            for (int nt = 0; nt < 8; nt++)
                #pragma unroll
                for (int r = 0; r < 4; r++) s[mt][nt][r] = 0.f;

        #pragma unroll
        for (int ks = 0; ks < 4; ks++) {
            const int kc16 = ks << 4;
            uint32_t bk[8][2];
            #pragma unroll
            for (int j = 0; j < 4; j++) {
                const uint32_t ad = s2u(K + ((j << 4) + rBp) * KH_ST + kc16 + cBp);
                LDSM_X4(bk[2*j][0], bk[2*j][1], bk[2*j+1][0], bk[2*j+1][1], ad);
            }
            #pragma unroll
            for (int nt = 0; nt < 8; nt++) {
                mma_f16(s[0][nt], qA[0][ks][0], qA[0][ks][1], qA[0][ks][2], qA[0][ks][3],
                        bk[nt][0], bk[nt][1]);
                mma_f16(s[1][nt], qA[1][ks][0], qA[1][ks][1], qA[1][ks][2], qA[1][ks][3],
                        bk[nt][0], bk[nt][1]);
            }
        }

        // ---- scale + mask + online softmax per m-tile ----
        #pragma unroll
        for (int mt = 0; mt < 2; mt++) {
            #pragma unroll
            for (int nt = 0; nt < 8; nt++) {
                s[mt][nt][0] = mk[mt][0][nt].x ? -1e30f : s[mt][nt][0] * 0.125f;
                s[mt][nt][1] = mk[mt][0][nt].y ? -1e30f : s[mt][nt][1] * 0.125f;
                s[mt][nt][2] = mk[mt][1][nt].x ? -1e30f : s[mt][nt][2] * 0.125f;
                s[mt][nt][3] = mk[mt][1][nt].y ? -1e30f : s[mt][nt][3] * 0.125f;
            }
            float mlo = -1e30f, mhi = -1e30f;
            #pragma unroll
            for (int nt = 0; nt < 8; nt++) {
                mlo = fmaxf(mlo, fmaxf(s[mt][nt][0], s[mt][nt][1]));
                mhi = fmaxf(mhi, fmaxf(s[mt][nt][2], s[mt][nt][3]));
            }
            mlo = fmaxf(mlo, __shfl_xor_sync(0xffffffffu, mlo, 1));
            mlo = fmaxf(mlo, __shfl_xor_sync(0xffffffffu, mlo, 2));
            mhi = fmaxf(mhi, __shfl_xor_sync(0xffffffffu, mhi, 1));
            mhi = fmaxf(mhi, __shfl_xor_sync(0xffffffffu, mhi, 2));

            const float mn0 = fmaxf(mrun[mt][0], mlo);
            const float mn1 = fmaxf(mrun[mt][1], mhi);
            const float al0 = __expf(mrun[mt][0] - mn0);
            const float al1 = __expf(mrun[mt][1] - mn1);
            mrun[mt][0] = mn0; mrun[mt][1] = mn1;

            float rs0 = 0.f, rs1 = 0.f;
            #pragma unroll
            for (int nt = 0; nt < 8; nt++) {
                s[mt][nt][0] = __expf(s[mt][nt][0] - mn0);
                s[mt][nt][1] = __expf(s[mt][nt][1] - mn0);
                s[mt][nt][2] = __expf(s[mt][nt][2] - mn1);
                s[mt][nt][3] = __expf(s[mt][nt][3] - mn1);
                rs0 += s[mt][nt][0] + s[mt][nt][1];
                rs1 += s[mt][nt][2] + s[mt][nt][3];
            }
            rs0 += __shfl_xor_sync(0xffffffffu, rs0, 1);
            rs0 += __shfl_xor_sync(0xffffffffu, rs0, 2);
            rs1 += __shfl_xor_sync(0xffffffffu, rs1, 1);
            rs1 += __shfl_xor_sync(0xffffffffu, rs1, 2);
            lrun[mt][0] = lrun[mt][0] * al0 + rs0;
            lrun[mt][1] = lrun[mt][1] * al1 + rs1;

            #pragma unroll
            for (int nt = 0; nt < 8; nt++) {
                accO[mt][nt][0] *= al0; accO[mt][nt][1] *= al0;
                accO[mt][nt][2] *= al1; accO[mt][nt][3] *= al1;
            }
        }

        // ---- O += P V : P frag register-resident; V frag via ldmatrix.trans --
        #pragma unroll
        for (int kc = 0; kc < 4; kc++) {
            uint32_t pa[2][4];
            #pragma unroll
            for (int mt = 0; mt < 2; mt++) {
                pa[mt][0] = f2h2(s[mt][2*kc  ][0], s[mt][2*kc  ][1]);
                pa[mt][1] = f2h2(s[mt][2*kc  ][2], s[mt][2*kc  ][3]);
                pa[mt][2] = f2h2(s[mt][2*kc+1][0], s[mt][2*kc+1][1]);
                pa[mt][3] = f2h2(s[mt][2*kc+1][2], s[mt][2*kc+1][3]);
            }
            const int keyc = kc << 4;
            uint32_t bv[8][2];
            #pragma unroll
            for (int j = 0; j < 4; j++) {
                const uint32_t ad = s2u(V + (keyc + rAp) * KH_ST + (j << 4) + cAp);
                LDSM_X4_T(bv[2*j][0], bv[2*j][1], bv[2*j+1][0], bv[2*j+1][1], ad);
            }
            #pragma unroll
            for (int nt = 0; nt < 8; nt++) {
                mma_f16(accO[0][nt], pa[0][0], pa[0][1], pa[0][2], pa[0][3],
                        bv[nt][0], bv[nt][1]);
                mma_f16(accO[1][nt], pa[1][0], pa[1][1], pa[1][2], pa[1][3],
                        bv[nt][0], bv[nt][1]);
            }
        }
        __syncthreads();
    }

    // ---- epilogue: write CTX in fp16 ----
    #pragma unroll
    for (int mt = 0; mt < 2; mt++) {
        const float inv0 = 1.0f / lrun[mt][0];
        const float inv1 = 1.0f / lrun[mt][1];
        __half* Cp = CTX + ((size_t)b * L_ + qrow + (mt << 4)) * E_ + (h << 6);
        #pragma unroll
        for (int nt = 0; nt < 8; nt++) {
            const int col = (nt << 3) + (qd << 1);
            *(uint32_t*)(Cp + col) =
                f2h2(accO[mt][nt][0] * inv0, accO[mt][nt][1] * inv0);
            *(uint32_t*)(Cp + (size_t)8 * E_ + col) =
                f2h2(accO[mt][nt][2] * inv1, accO[mt][nt][3] * inv1);
        }
    }
}

// ---------------- LayerNorm over E=1024, one row per block -----------------
__global__ __launch_bounds__(256) void ln_kernel(
    const float* __restrict__ X, const float* __restrict__ gamma,
    const float* __restrict__ beta, float* __restrict__ out)
{
    __shared__ float red[8];
    __shared__ float s_mu, s_rstd;
    const int row = blockIdx.x;
    const int t = threadIdx.x;

    float4 v = ((const float4*)(X + (size_t)row * E_))[t];
    float s = v.x + v.y + v.z + v.w;
    #pragma unroll
    for (int off = 16; off >= 1; off >>= 1) s += __shfl_xor_sync(0xffffffffu, s, off);
    if ((t & 31) == 0) red[t >> 5] = s;
    __syncthreads();
    if (t == 0) {
        float tot = 0.f;
        #pragma unroll
        for (int k = 0; k < 8; k++) tot += red[k];
        s_mu = tot * (1.0f / E_);
    }
    __syncthreads();
    const float mu = s_mu;

    float dx = v.x - mu, dy = v.y - mu, dz = v.z - mu, dw = v.w - mu;
    float sq = dx * dx + dy * dy + dz * dz + dw * dw;
    #pragma unroll
    for (int off = 16; off >= 1; off >>= 1) sq += __shfl_xor_sync(0xffffffffu, sq, off);
    __syncthreads();
    if ((t & 31) == 0) red[t >> 5] = sq;
    __syncthreads();
    if (t == 0) {
        float tot = 0.f;
        #pragma unroll
        for (int k = 0; k < 8; k++) tot += red[k];
        s_rstd = rsqrtf(tot * (1.0f / E_) + 1e-6f);
    }
    __syncthreads();
    const float rstd = s_rstd;

    float4 g  = ((const float4*)gamma)[t];
    float4 be = ((const float4*)beta)[t];
    float4 o;
    o.x = dx * rstd * g.x + be.x;
    o.y = dy * rstd * g.y + be.y;
    o.z = dz * rstd * g.z + be.z;
    o.w = dw * rstd * g.w + be.w;
    ((float4*)(out + (size_t)row * E_))[t] = o;
}

// ---------------- launch ---------------------------------------------------
extern "C" void kernel_launch(void* const* d_in, const int* in_sizes, int n_in,
                              void* d_out, int out_size)
{
    const float* xq    = (const float*)d_in[0];
    const float* xk    = (const float*)d_in[1];
    const float* xv    = (const float*)d_in[2];
    const unsigned char* mask = (const unsigned char*)d_in[3];
    const float* Wq = (const float*)d_in[4];
    const float* bq = (const float*)d_in[5];
    const float* Wk = (const float*)d_in[6];
    const float* bk = (const float*)d_in[7];
    const float* Wv = (const float*)d_in[8];
    const float* bv = (const float*)d_in[9];
    const float* Wo = (const float*)d_in[10];
    const float* bo = (const float*)d_in[11];
    const float* gamma = (const float*)d_in[12];
    const float* beta  = (const float*)d_in[13];
    float* out = (float*)d_out;

    __half *dQ, *dK, *dV, *dCTX;
    float *dPROJ;
    cudaGetSymbolAddress((void**)&dQ,    g_Qh);
    cudaGetSymbolAddress((void**)&dK,    g_Kh);
    cudaGetSymbolAddress((void**)&dV,    g_Vh);
    cudaGetSymbolAddress((void**)&dCTX,  g_CTXh);
    cudaGetSymbolAddress((void**)&dPROJ, g_PROJ);

    cudaFuncSetAttribute(gemm_qkv,
                         cudaFuncAttributeMaxDynamicSharedMemorySize, GEMM_SMEM);
    cudaFuncSetAttribute(gemm_o,
                         cudaFuncAttributeMaxDynamicSharedMemorySize, GEMM_SMEM);
    cudaFuncSetAttribute(attn_tc,
                         cudaFuncAttributeMaxDynamicSharedMemorySize, ATTN_SMEM);

    // fp32 -> fp16 conversion (x inputs + weights)
    f2h_kernel<<<dim3((M_*E_/4 + 255)/256, 1, 7), 256>>>(
        xq, xk, xv, Wq, Wk, Wv, Wo);

    gemm_qkv<<<dim3(E_ / 128, M_ / 128, 3), 256, GEMM_SMEM>>>(
        dQ, dK, dV, bq, bk, bv);

    attn_tc<<<dim3(L_ / 128, H_, B_), 128, ATTN_SMEM>>>(dQ, dK, dV, mask, dCTX);

    gemm_o<<<dim3(E_ / 128, M_ / 128), 256, GEMM_SMEM>>>(bo, xq, dPROJ);

    ln_kernel<<<M_, 256>>>(dPROJ, gamma, beta, out);
}